// round 2
// baseline (speedup 1.0000x reference)
#include <cuda_runtime.h>
#include <math_constants.h>

// ---------------- problem constants ----------------
#define C_DIM   512
#define NGROUPS 32
#define GSIZE   16          // C_DIM / NGROUPS
#define BATCH   4
#define HW      4096        // 64*64 tokens per batch
#define NTOK    16384       // BATCH*HW
#define EPS     1e-6f
#define SM_SCALE 0.04419417382415922f   // 512^-0.5

// ---------------- device scratch ----------------
__device__ float g_mean[BATCH * NGROUPS];
__device__ float g_rstd[BATCH * NGROUPS];
__device__ float g_hn[NTOK * C_DIM];                     // 32 MB
__device__ float g_q [NTOK * C_DIM];                     // 32 MB
__device__ float g_k [NTOK * C_DIM];                     // 32 MB
__device__ float g_v [NTOK * C_DIM];                     // 32 MB
__device__ float g_s [(size_t)BATCH * HW * HW];          // 256 MB
__device__ float g_o [NTOK * C_DIM];                     // 32 MB

// ---------------- GroupNorm stats ----------------
// one block per (batch, group); reduce 4096 pixels * 16 channels
__global__ void gn_stats_kernel(const float* __restrict__ x) {
    int bg = blockIdx.x;                 // 0..127
    int b  = bg / NGROUPS;
    int g  = bg % NGROUPS;
    const float* base = x + (size_t)b * HW * C_DIM + g * GSIZE;

    float s = 0.f, ss = 0.f;
    for (int p = threadIdx.x; p < HW; p += blockDim.x) {
        const float4* v4 = (const float4*)(base + (size_t)p * C_DIM);
        #pragma unroll
        for (int j = 0; j < 4; j++) {
            float4 v = v4[j];
            s  += v.x + v.y + v.z + v.w;
            ss += v.x*v.x + v.y*v.y + v.z*v.z + v.w*v.w;
        }
    }
    // block reduce (256 threads = 8 warps)
    __shared__ float shs[8], shss[8];
    int lane = threadIdx.x & 31, wid = threadIdx.x >> 5;
    #pragma unroll
    for (int o = 16; o > 0; o >>= 1) {
        s  += __shfl_xor_sync(0xffffffffu, s,  o);
        ss += __shfl_xor_sync(0xffffffffu, ss, o);
    }
    if (lane == 0) { shs[wid] = s; shss[wid] = ss; }
    __syncthreads();
    if (threadIdx.x == 0) {
        float ts = 0.f, tss = 0.f;
        #pragma unroll
        for (int i = 0; i < 8; i++) { ts += shs[i]; tss += shss[i]; }
        const float invn = 1.0f / (float)(HW * GSIZE);
        float mean = ts * invn;
        float var  = tss * invn - mean * mean;
        g_mean[bg] = mean;
        g_rstd[bg] = rsqrtf(var + EPS);
    }
}

// ---------------- GroupNorm apply ----------------
__global__ void gn_apply_kernel(const float* __restrict__ x,
                                const float* __restrict__ scale,
                                const float* __restrict__ bias) {
    size_t i = (size_t)blockIdx.x * blockDim.x + threadIdx.x;   // float4 index
    int    c4 = (int)(i % (C_DIM / 4));
    size_t t  = i / (C_DIM / 4);
    int    b  = (int)(t / HW);
    int    g  = (c4 * 4) / GSIZE;

    float mean = g_mean[b * NGROUPS + g];
    float rstd = g_rstd[b * NGROUPS + g];
    float4 xv = ((const float4*)x)[i];
    float4 sc = ((const float4*)scale)[c4];
    float4 bi = ((const float4*)bias)[c4];
    float4 r;
    r.x = (xv.x - mean) * rstd * sc.x + bi.x;
    r.y = (xv.y - mean) * rstd * sc.y + bi.y;
    r.z = (xv.z - mean) * rstd * sc.z + bi.z;
    r.w = (xv.w - mean) * rstd * sc.w + bi.w;
    ((float4*)g_hn)[i] = r;
}

// ---------------- SGEMM: C = alpha * A @ B(^T) [+ bias] [+ res] ----------------
// A: [M,K] row-major. B: row-major [K,N] (BTRANS=false) or [N,K] (BTRANS=true).
// 128x128x8 tiles, 8x8 per thread, 256 threads. All dims divisible (no guards).
template<bool BTRANS, bool HAS_BIAS, bool HAS_RES>
__global__ void __launch_bounds__(256)
sgemm128(const float* __restrict__ A, const float* __restrict__ B,
         const float* __restrict__ bias, const float* __restrict__ res,
         float* __restrict__ C,
         int M, int N, int K, float alpha,
         size_t sA, size_t sB, size_t sC) {
    constexpr int BM = 128, BN = 128, BK = 8, TM = 8, TN = 8;
    __shared__ float As[BK][BM];
    __shared__ float Bs[BK][BN];

    A += (size_t)blockIdx.z * sA;
    B += (size_t)blockIdx.z * sB;
    C += (size_t)blockIdx.z * sC;
    if (HAS_RES) res += (size_t)blockIdx.z * sC;

    const int bm = blockIdx.y * BM;
    const int bn = blockIdx.x * BN;
    const int tid = threadIdx.x;
    const int tx = tid % 16, ty = tid / 16;

    const int arow = tid / 2;             // 0..127
    const int acol = (tid % 2) * 4;       // 0 or 4
    const int brow = tid / 32;            // 0..7
    const int bcol = (tid % 32) * 4;      // 0..124

    float acc[TM][TN] = {};

    for (int k0 = 0; k0 < K; k0 += BK) {
        float4 av = *(const float4*)(A + (size_t)(bm + arow) * K + k0 + acol);
        As[acol + 0][arow] = av.x;
        As[acol + 1][arow] = av.y;
        As[acol + 2][arow] = av.z;
        As[acol + 3][arow] = av.w;

        if (BTRANS) {
            float4 bv = *(const float4*)(B + (size_t)(bn + arow) * K + k0 + acol);
            Bs[acol + 0][arow] = bv.x;
            Bs[acol + 1][arow] = bv.y;
            Bs[acol + 2][arow] = bv.z;
            Bs[acol + 3][arow] = bv.w;
        } else {
            float4 bv = *(const float4*)(B + (size_t)(k0 + brow) * N + bn + bcol);
            *(float4*)&Bs[brow][bcol] = bv;
        }
        __syncthreads();

        #pragma unroll
        for (int kk = 0; kk < BK; kk++) {
            float4 a0 = *(const float4*)&As[kk][ty * TM];
            float4 a1 = *(const float4*)&As[kk][ty * TM + 4];
            float4 b0 = *(const float4*)&Bs[kk][tx * TN];
            float4 b1 = *(const float4*)&Bs[kk][tx * TN + 4];
            float a[TM] = {a0.x, a0.y, a0.z, a0.w, a1.x, a1.y, a1.z, a1.w};
            float bb[TN] = {b0.x, b0.y, b0.z, b0.w, b1.x, b1.y, b1.z, b1.w};
            #pragma unroll
            for (int i = 0; i < TM; i++)
                #pragma unroll
                for (int j = 0; j < TN; j++)
                    acc[i][j] += a[i] * bb[j];
        }
        __syncthreads();
    }

    // epilogue
    #pragma unroll
    for (int i = 0; i < TM; i++) {
        int row = bm + ty * TM + i;
        #pragma unroll
        for (int j = 0; j < TN; j += 4) {
            int col = bn + tx * TN + j;
            float4 r;
            r.x = acc[i][j + 0] * alpha;
            r.y = acc[i][j + 1] * alpha;
            r.z = acc[i][j + 2] * alpha;
            r.w = acc[i][j + 3] * alpha;
            if (HAS_BIAS) {
                float4 bb = *(const float4*)(bias + col);
                r.x += bb.x; r.y += bb.y; r.z += bb.z; r.w += bb.w;
            }
            if (HAS_RES) {
                float4 rr = *(const float4*)(res + (size_t)row * N + col);
                r.x += rr.x; r.y += rr.y; r.z += rr.z; r.w += rr.w;
            }
            *(float4*)(C + (size_t)row * N + col) = r;
        }
    }
}

// ---------------- row softmax over 4096 keys ----------------
// one block (256 threads) per row; 16 values per thread live in registers
__global__ void softmax_rows_kernel(float* __restrict__ S) {
    float* p = S + (size_t)blockIdx.x * HW;
    const int tid = threadIdx.x;
    const int lane = tid & 31, wid = tid >> 5;
    __shared__ float shm[8], shs[8];
    __shared__ float bmax, bsum;

    float v[16];
    float mx = -CUDART_INF_F;
    #pragma unroll
    for (int i = 0; i < 4; i++) {
        float4 t = *(const float4*)(p + i * 1024 + tid * 4);
        v[i * 4 + 0] = t.x; v[i * 4 + 1] = t.y;
        v[i * 4 + 2] = t.z; v[i * 4 + 3] = t.w;
        mx = fmaxf(mx, fmaxf(fmaxf(t.x, t.y), fmaxf(t.z, t.w)));
    }
    #pragma unroll
    for (int o = 16; o > 0; o >>= 1) mx = fmaxf(mx, __shfl_xor_sync(0xffffffffu, mx, o));
    if (lane == 0) shm[wid] = mx;
    __syncthreads();
    if (tid == 0) {
        float t = shm[0];
        #pragma unroll
        for (int i = 1; i < 8; i++) t = fmaxf(t, shm[i]);
        bmax = t;
    }
    __syncthreads();
    mx = bmax;

    float sum = 0.f;
    #pragma unroll
    for (int i = 0; i < 16; i++) { v[i] = expf(v[i] - mx); sum += v[i]; }
    #pragma unroll
    for (int o = 16; o > 0; o >>= 1) sum += __shfl_xor_sync(0xffffffffu, sum, o);
    if (lane == 0) shs[wid] = sum;
    __syncthreads();
    if (tid == 0) {
        float t = 0.f;
        #pragma unroll
        for (int i = 0; i < 8; i++) t += shs[i];
        bsum = 1.0f / t;
    }
    __syncthreads();
    const float inv = bsum;

    #pragma unroll
    for (int i = 0; i < 4; i++) {
        float4 t;
        t.x = v[i * 4 + 0] * inv; t.y = v[i * 4 + 1] * inv;
        t.z = v[i * 4 + 2] * inv; t.w = v[i * 4 + 3] * inv;
        *(float4*)(p + i * 1024 + tid * 4) = t;
    }
}

// ---------------- launch ----------------
extern "C" void kernel_launch(void* const* d_in, const int* in_sizes, int n_in,
                              void* d_out, int out_size) {
    const float* x        = (const float*)d_in[0];
    const float* gn_scale = (const float*)d_in[1];
    const float* gn_bias  = (const float*)d_in[2];
    const float* wq = (const float*)d_in[3];  const float* bq = (const float*)d_in[4];
    const float* wk = (const float*)d_in[5];  const float* bk = (const float*)d_in[6];
    const float* wv = (const float*)d_in[7];  const float* bv = (const float*)d_in[8];
    const float* wo = (const float*)d_in[9];  const float* bo = (const float*)d_in[10];
    float* out = (float*)d_out;

    float *hn, *q, *kb, *v, *s, *o;
    cudaGetSymbolAddress((void**)&hn, g_hn);
    cudaGetSymbolAddress((void**)&q,  g_q);
    cudaGetSymbolAddress((void**)&kb, g_k);
    cudaGetSymbolAddress((void**)&v,  g_v);
    cudaGetSymbolAddress((void**)&s,  g_s);
    cudaGetSymbolAddress((void**)&o,  g_o);

    // 1) GroupNorm
    gn_stats_kernel<<<BATCH * NGROUPS, 256>>>(x);
    gn_apply_kernel<<<(NTOK * C_DIM / 4) / 256, 256>>>(x, gn_scale, gn_bias);

    dim3 blk(256);
    // 2) QKV projections: [16384,512] @ [512,512] + bias
    dim3 gproj(C_DIM / 128, NTOK / 128, 1);
    sgemm128<false, true, false><<<gproj, blk>>>(hn, wq, bq, nullptr, q,
        NTOK, C_DIM, C_DIM, 1.0f, 0, 0, 0);
    sgemm128<false, true, false><<<gproj, blk>>>(hn, wk, bk, nullptr, kb,
        NTOK, C_DIM, C_DIM, 1.0f, 0, 0, 0);
    sgemm128<false, true, false><<<gproj, blk>>>(hn, wv, bv, nullptr, v,
        NTOK, C_DIM, C_DIM, 1.0f, 0, 0, 0);

    // 3) S = (Q @ K^T) * c^-0.5, batched over 4
    dim3 gs(HW / 128, HW / 128, BATCH);
    sgemm128<true, false, false><<<gs, blk>>>(q, kb, nullptr, nullptr, s,
        HW, HW, C_DIM, SM_SCALE,
        (size_t)HW * C_DIM, (size_t)HW * C_DIM, (size_t)HW * HW);

    // 4) softmax over keys
    softmax_rows_kernel<<<NTOK, 256>>>(s);

    // 5) O = P @ V, batched over 4
    dim3 gpv(C_DIM / 128, HW / 128, BATCH);
    sgemm128<false, false, false><<<gpv, blk>>>(s, v, nullptr, nullptr, o,
        HW, C_DIM, HW, 1.0f,
        (size_t)HW * HW, (size_t)HW * C_DIM, (size_t)HW * C_DIM);

    // 6) out = x + O @ wo + bo
    sgemm128<false, true, true><<<gproj, blk>>>(o, wo, bo, x, out,
        NTOK, C_DIM, C_DIM, 1.0f, 0, 0, 0);
}

// round 3
// speedup vs baseline: 3.1965x; 3.1965x over previous
#include <cuda_runtime.h>
#include <math_constants.h>
#include <cstdint>

// ---------------- problem constants ----------------
#define C_DIM   512
#define NGROUPS 32
#define GSIZE   16
#define BATCH   4
#define HW      4096
#define NTOK    16384
#define EPS     1e-6f
#define SM_SCALE 0.04419417382415922f   // 512^-0.5

// ---------------- device scratch ----------------
__device__ float g_mean[BATCH * NGROUPS];
__device__ float g_rstd[BATCH * NGROUPS];
__device__ float g_hn[NTOK * C_DIM];
__device__ float g_q [NTOK * C_DIM];
__device__ float g_k [NTOK * C_DIM];
__device__ float g_v [NTOK * C_DIM];
__device__ float g_s [(size_t)BATCH * HW * HW];   // 256 MB
__device__ float g_o [NTOK * C_DIM];
__device__ float g_wr[4 * C_DIM * C_DIM];         // tf32-rounded weights

// ---------------- helpers ----------------
__device__ __forceinline__ float tf32r(float x) {
    unsigned u;
    asm("cvt.rna.tf32.f32 %0, %1;" : "=r"(u) : "f"(x));
    return __uint_as_float(u);
}
__device__ __forceinline__ uint32_t smem_u32(const void* p) {
    return (uint32_t)__cvta_generic_to_shared(p);
}
#define CP_ASYNC16(dst, src) \
    asm volatile("cp.async.cg.shared.global [%0], [%1], 16;" :: "r"(dst), "l"(src))
#define CP_COMMIT() asm volatile("cp.async.commit_group;")

__device__ __forceinline__ void mma_tf32(float& c0, float& c1, float& c2, float& c3,
                                         uint32_t a0, uint32_t a1, uint32_t a2, uint32_t a3,
                                         uint32_t b0, uint32_t b1) {
    asm volatile(
        "mma.sync.aligned.m16n8k8.row.col.f32.tf32.tf32.f32 "
        "{%0,%1,%2,%3}, {%4,%5,%6,%7}, {%8,%9}, {%0,%1,%2,%3};"
        : "+f"(c0), "+f"(c1), "+f"(c2), "+f"(c3)
        : "r"(a0), "r"(a1), "r"(a2), "r"(a3), "r"(b0), "r"(b1));
}

// ---------------- GroupNorm stats ----------------
__global__ void gn_stats_kernel(const float* __restrict__ x) {
    int bg = blockIdx.x;
    int b  = bg / NGROUPS;
    int g  = bg % NGROUPS;
    const float* base = x + (size_t)b * HW * C_DIM + g * GSIZE;

    float s = 0.f, ss = 0.f;
    for (int p = threadIdx.x; p < HW; p += blockDim.x) {
        const float4* v4 = (const float4*)(base + (size_t)p * C_DIM);
        #pragma unroll
        for (int j = 0; j < 4; j++) {
            float4 v = v4[j];
            s  += v.x + v.y + v.z + v.w;
            ss += v.x*v.x + v.y*v.y + v.z*v.z + v.w*v.w;
        }
    }
    __shared__ float shs[8], shss[8];
    int lane = threadIdx.x & 31, wid = threadIdx.x >> 5;
    #pragma unroll
    for (int o = 16; o > 0; o >>= 1) {
        s  += __shfl_xor_sync(0xffffffffu, s,  o);
        ss += __shfl_xor_sync(0xffffffffu, ss, o);
    }
    if (lane == 0) { shs[wid] = s; shss[wid] = ss; }
    __syncthreads();
    if (threadIdx.x == 0) {
        float ts = 0.f, tss = 0.f;
        #pragma unroll
        for (int i = 0; i < 8; i++) { ts += shs[i]; tss += shss[i]; }
        const float invn = 1.0f / (float)(HW * GSIZE);
        float mean = ts * invn;
        float var  = tss * invn - mean * mean;
        g_mean[bg] = mean;
        g_rstd[bg] = rsqrtf(var + EPS);
    }
}

// ---------------- GroupNorm apply (writes tf32-rounded hn) ----------------
__global__ void gn_apply_kernel(const float* __restrict__ x,
                                const float* __restrict__ scale,
                                const float* __restrict__ bias) {
    size_t i = (size_t)blockIdx.x * blockDim.x + threadIdx.x;
    int    c4 = (int)(i % (C_DIM / 4));
    size_t t  = i / (C_DIM / 4);
    int    b  = (int)(t / HW);
    int    g  = (c4 * 4) / GSIZE;

    float mean = g_mean[b * NGROUPS + g];
    float rstd = g_rstd[b * NGROUPS + g];
    float4 xv = ((const float4*)x)[i];
    float4 sc = ((const float4*)scale)[c4];
    float4 bi = ((const float4*)bias)[c4];
    float4 r;
    r.x = tf32r((xv.x - mean) * rstd * sc.x + bi.x);
    r.y = tf32r((xv.y - mean) * rstd * sc.y + bi.y);
    r.z = tf32r((xv.z - mean) * rstd * sc.z + bi.z);
    r.w = tf32r((xv.w - mean) * rstd * sc.w + bi.w);
    ((float4*)g_hn)[i] = r;
}

// ---------------- round weights to tf32 ----------------
__global__ void round_weights_kernel(const float* __restrict__ w0,
                                     const float* __restrict__ w1,
                                     const float* __restrict__ w2,
                                     const float* __restrict__ w3) {
    int i = blockIdx.x * blockDim.x + threadIdx.x;   // < 512*512
    g_wr[0 * C_DIM * C_DIM + i] = tf32r(w0[i]);
    g_wr[1 * C_DIM * C_DIM + i] = tf32r(w1[i]);
    g_wr[2 * C_DIM * C_DIM + i] = tf32r(w2[i]);
    g_wr[3 * C_DIM * C_DIM + i] = tf32r(w3[i]);
}

// ---------------- TF32 tensor-core GEMM ----------------
// C = alpha * A @ B(^T) [+ bias] [+ res], optionally tf32-rounding the output.
// A: [M,K] row-major (tf32-rounded). B: [K,N] (BTRANS=0) or [N,K] (BTRANS=1).
// 128x128x16 block tile, 8 warps (2x4), 64x32 warp tile, cp.async double buffer.
template<bool BTRANS, bool HAS_BIAS, bool HAS_RES, bool ROUND_OUT>
__global__ void __launch_bounds__(256, 2)
gemm_tf32(const float* __restrict__ A, const float* __restrict__ B,
          const float* __restrict__ bias, const float* __restrict__ res,
          float* __restrict__ C,
          int M, int N, int K, float alpha,
          size_t sA, size_t sB, size_t sC) {
    constexpr int BM = 128, BN = 128, BK = 16;
    constexpr int ASTR = 20;                       // padded row stride (floats)
    constexpr int BROWS = BTRANS ? 128 : 16;
    constexpr int BSTR  = BTRANS ? 20 : 136;

    __shared__ float As[2][BM * ASTR];
    __shared__ float Bs[2][BROWS * BSTR];

    A += (size_t)blockIdx.z * sA;
    B += (size_t)blockIdx.z * sB;
    C += (size_t)blockIdx.z * sC;
    if (HAS_RES) res += (size_t)blockIdx.z * sC;

    const int bm = blockIdx.y * BM;
    const int bn = blockIdx.x * BN;
    const int tid  = threadIdx.x;
    const int lane = tid & 31;
    const int wid  = tid >> 5;
    const int g    = lane >> 2;     // groupID
    const int t    = lane & 3;      // threadID_in_group
    const int wm   = wid >> 2;      // 0..1 -> m offset *64
    const int wn   = wid & 3;       // 0..3 -> n offset *32

    float acc[4][4][4];
    #pragma unroll
    for (int i = 0; i < 4; i++)
        #pragma unroll
        for (int j = 0; j < 4; j++)
            #pragma unroll
            for (int r = 0; r < 4; r++) acc[i][j][r] = 0.f;

    auto load_stage = [&](int stage, int k0) {
        // A tile: 128 rows x 16 floats = 512 x 16B chunks
        #pragma unroll
        for (int i = 0; i < 2; i++) {
            int c = tid + i * 256;
            int row = c >> 2, kq = (c & 3) * 4;
            CP_ASYNC16(smem_u32(&As[stage][row * ASTR + kq]),
                       A + (size_t)(bm + row) * K + k0 + kq);
        }
        if (BTRANS) {
            #pragma unroll
            for (int i = 0; i < 2; i++) {
                int c = tid + i * 256;
                int row = c >> 2, kq = (c & 3) * 4;
                CP_ASYNC16(smem_u32(&Bs[stage][row * BSTR + kq]),
                           B + (size_t)(bn + row) * K + k0 + kq);
            }
        } else {
            #pragma unroll
            for (int i = 0; i < 2; i++) {
                int c = tid + i * 256;
                int row = c >> 5, nq = (c & 31) * 4;
                CP_ASYNC16(smem_u32(&Bs[stage][row * BSTR + nq]),
                           B + (size_t)(k0 + row) * N + bn + nq);
            }
        }
        CP_COMMIT();
    };

    const int nIter = K / BK;
    load_stage(0, 0);

    for (int it = 0; it < nIter; it++) {
        if (it + 1 < nIter) {
            load_stage((it + 1) & 1, (it + 1) * BK);
            asm volatile("cp.async.wait_group 1;");
        } else {
            asm volatile("cp.async.wait_group 0;");
        }
        __syncthreads();

        const float* as = As[it & 1];
        const float* bs = Bs[it & 1];

        #pragma unroll
        for (int ks = 0; ks < 2; ks++) {
            uint32_t af[4][4], bf[4][2];
            #pragma unroll
            for (int mt = 0; mt < 4; mt++) {
                int r = wm * 64 + mt * 16 + g;
                int kc = ks * 8 + t;
                af[mt][0] = __float_as_uint(as[r * ASTR + kc]);
                af[mt][1] = __float_as_uint(as[(r + 8) * ASTR + kc]);
                af[mt][2] = __float_as_uint(as[r * ASTR + kc + 4]);
                af[mt][3] = __float_as_uint(as[(r + 8) * ASTR + kc + 4]);
            }
            #pragma unroll
            for (int nt = 0; nt < 4; nt++) {
                int n = wn * 32 + nt * 8 + g;
                int kc = ks * 8 + t;
                if (BTRANS) {
                    bf[nt][0] = __float_as_uint(bs[n * BSTR + kc]);
                    bf[nt][1] = __float_as_uint(bs[n * BSTR + kc + 4]);
                } else {
                    bf[nt][0] = __float_as_uint(bs[kc * BSTR + n]);
                    bf[nt][1] = __float_as_uint(bs[(kc + 4) * BSTR + n]);
                }
            }
            #pragma unroll
            for (int mt = 0; mt < 4; mt++)
                #pragma unroll
                for (int nt = 0; nt < 4; nt++)
                    mma_tf32(acc[mt][nt][0], acc[mt][nt][1], acc[mt][nt][2], acc[mt][nt][3],
                             af[mt][0], af[mt][1], af[mt][2], af[mt][3],
                             bf[nt][0], bf[nt][1]);
        }
        __syncthreads();
    }

    // epilogue: c0,c1 -> (r0, col..col+1); c2,c3 -> (r0+8, col..col+1)
    #pragma unroll
    for (int mt = 0; mt < 4; mt++) {
        int r0 = bm + wm * 64 + mt * 16 + g;
        #pragma unroll
        for (int nt = 0; nt < 4; nt++) {
            int col = bn + wn * 32 + nt * 8 + 2 * t;
            float2 bb = make_float2(0.f, 0.f);
            if (HAS_BIAS) bb = *(const float2*)(bias + col);

            float v0 = acc[mt][nt][0] * alpha + bb.x;
            float v1 = acc[mt][nt][1] * alpha + bb.y;
            float v2 = acc[mt][nt][2] * alpha + bb.x;
            float v3 = acc[mt][nt][3] * alpha + bb.y;
            if (HAS_RES) {
                float2 ra = *(const float2*)(res + (size_t)r0 * N + col);
                float2 rb = *(const float2*)(res + (size_t)(r0 + 8) * N + col);
                v0 += ra.x; v1 += ra.y; v2 += rb.x; v3 += rb.y;
            }
            if (ROUND_OUT) {
                v0 = tf32r(v0); v1 = tf32r(v1); v2 = tf32r(v2); v3 = tf32r(v3);
            }
            *(float2*)(C + (size_t)r0 * N + col)       = make_float2(v0, v1);
            *(float2*)(C + (size_t)(r0 + 8) * N + col) = make_float2(v2, v3);
        }
    }
}

// ---------------- row softmax over 4096 keys (writes tf32-rounded P) ----------------
__global__ void softmax_rows_kernel(float* __restrict__ S) {
    float* p = S + (size_t)blockIdx.x * HW;
    const int tid = threadIdx.x;
    const int lane = tid & 31, wid = tid >> 5;
    __shared__ float shm[8], shs[8];
    __shared__ float bmax, bsum;

    float v[16];
    float mx = -CUDART_INF_F;
    #pragma unroll
    for (int i = 0; i < 4; i++) {
        float4 t = *(const float4*)(p + i * 1024 + tid * 4);
        v[i * 4 + 0] = t.x; v[i * 4 + 1] = t.y;
        v[i * 4 + 2] = t.z; v[i * 4 + 3] = t.w;
        mx = fmaxf(mx, fmaxf(fmaxf(t.x, t.y), fmaxf(t.z, t.w)));
    }
    #pragma unroll
    for (int o = 16; o > 0; o >>= 1) mx = fmaxf(mx, __shfl_xor_sync(0xffffffffu, mx, o));
    if (lane == 0) shm[wid] = mx;
    __syncthreads();
    if (tid == 0) {
        float t = shm[0];
        #pragma unroll
        for (int i = 1; i < 8; i++) t = fmaxf(t, shm[i]);
        bmax = t;
    }
    __syncthreads();
    mx = bmax;

    float sum = 0.f;
    #pragma unroll
    for (int i = 0; i < 16; i++) { v[i] = expf(v[i] - mx); sum += v[i]; }
    #pragma unroll
    for (int o = 16; o > 0; o >>= 1) sum += __shfl_xor_sync(0xffffffffu, sum, o);
    if (lane == 0) shs[wid] = sum;
    __syncthreads();
    if (tid == 0) {
        float t = 0.f;
        #pragma unroll
        for (int i = 0; i < 8; i++) t += shs[i];
        bsum = 1.0f / t;
    }
    __syncthreads();
    const float inv = bsum;

    #pragma unroll
    for (int i = 0; i < 4; i++) {
        float4 t;
        t.x = tf32r(v[i * 4 + 0] * inv); t.y = tf32r(v[i * 4 + 1] * inv);
        t.z = tf32r(v[i * 4 + 2] * inv); t.w = tf32r(v[i * 4 + 3] * inv);
        *(float4*)(p + i * 1024 + tid * 4) = t;
    }
}

// ---------------- launch ----------------
extern "C" void kernel_launch(void* const* d_in, const int* in_sizes, int n_in,
                              void* d_out, int out_size) {
    const float* x        = (const float*)d_in[0];
    const float* gn_scale = (const float*)d_in[1];
    const float* gn_bias  = (const float*)d_in[2];
    const float* wq = (const float*)d_in[3];  const float* bq = (const float*)d_in[4];
    const float* wk = (const float*)d_in[5];  const float* bk = (const float*)d_in[6];
    const float* wv = (const float*)d_in[7];  const float* bv = (const float*)d_in[8];
    const float* wo = (const float*)d_in[9];  const float* bo = (const float*)d_in[10];
    float* out = (float*)d_out;

    float *hn, *q, *kb, *v, *s, *o, *wr;
    cudaGetSymbolAddress((void**)&hn, g_hn);
    cudaGetSymbolAddress((void**)&q,  g_q);
    cudaGetSymbolAddress((void**)&kb, g_k);
    cudaGetSymbolAddress((void**)&v,  g_v);
    cudaGetSymbolAddress((void**)&s,  g_s);
    cudaGetSymbolAddress((void**)&o,  g_o);
    cudaGetSymbolAddress((void**)&wr, g_wr);
    const float* wqr = wr + 0 * C_DIM * C_DIM;
    const float* wkr = wr + 1 * C_DIM * C_DIM;
    const float* wvr = wr + 2 * C_DIM * C_DIM;
    const float* wor = wr + 3 * C_DIM * C_DIM;

    // 1) GroupNorm + weight rounding
    gn_stats_kernel<<<BATCH * NGROUPS, 256>>>(x);
    gn_apply_kernel<<<(NTOK * C_DIM / 4) / 256, 256>>>(x, gn_scale, gn_bias);
    round_weights_kernel<<<(C_DIM * C_DIM) / 256, 256>>>(wq, wk, wv, wo);

    dim3 blk(256);
    // 2) QKV projections (outputs tf32-rounded)
    dim3 gproj(C_DIM / 128, NTOK / 128, 1);
    gemm_tf32<false, true, false, true><<<gproj, blk>>>(hn, wqr, bq, nullptr, q,
        NTOK, C_DIM, C_DIM, 1.0f, 0, 0, 0);
    gemm_tf32<false, true, false, true><<<gproj, blk>>>(hn, wkr, bk, nullptr, kb,
        NTOK, C_DIM, C_DIM, 1.0f, 0, 0, 0);
    gemm_tf32<false, true, false, true><<<gproj, blk>>>(hn, wvr, bv, nullptr, v,
        NTOK, C_DIM, C_DIM, 1.0f, 0, 0, 0);

    // 3) S = (Q @ K^T) * c^-0.5, batched
    dim3 gs(HW / 128, HW / 128, BATCH);
    gemm_tf32<true, false, false, false><<<gs, blk>>>(q, kb, nullptr, nullptr, s,
        HW, HW, C_DIM, SM_SCALE,
        (size_t)HW * C_DIM, (size_t)HW * C_DIM, (size_t)HW * HW);

    // 4) softmax (outputs tf32-rounded P)
    softmax_rows_kernel<<<NTOK, 256>>>(s);

    // 5) O = P @ V, batched (output tf32-rounded for final proj)
    dim3 gpv(C_DIM / 128, HW / 128, BATCH);
    gemm_tf32<false, false, false, true><<<gpv, blk>>>(s, v, nullptr, nullptr, o,
        HW, C_DIM, HW, 1.0f,
        (size_t)HW * HW, (size_t)HW * C_DIM, (size_t)HW * C_DIM);

    // 6) out = x + O @ wo + bo
    gemm_tf32<false, true, true, false><<<gproj, blk>>>(o, wor, bo, x, out,
        NTOK, C_DIM, C_DIM, 1.0f, 0, 0, 0);
}

// round 4
// speedup vs baseline: 6.2401x; 1.9522x over previous
#include <cuda_runtime.h>
#include <cuda_bf16.h>
#include <math_constants.h>
#include <cstdint>

// ---------------- problem constants ----------------
#define C_DIM   512
#define NGROUPS 32
#define GSIZE   16
#define BATCH   4
#define HW      4096
#define NTOK    16384
#define EPS     1e-6f
#define SM_SCALE 0.04419417382415922f   // 512^-0.5

typedef __nv_bfloat16 bf16;

// ---------------- device scratch ----------------
__device__ float g_mean[BATCH * NGROUPS];
__device__ float g_rstd[BATCH * NGROUPS];
__device__ bf16  g_hn[NTOK * C_DIM];
__device__ bf16  g_q [NTOK * C_DIM];
__device__ bf16  g_k [NTOK * C_DIM];
__device__ bf16  g_v [NTOK * C_DIM];
__device__ float g_s [(size_t)BATCH * HW * HW];    // fp32 scores, 256 MB
__device__ bf16  g_p [(size_t)BATCH * HW * HW];    // bf16 probs, 128 MB
__device__ bf16  g_o [NTOK * C_DIM];
__device__ bf16  g_wt[4 * C_DIM * C_DIM];          // transposed bf16 weights [n][k]

// ---------------- helpers ----------------
__device__ __forceinline__ uint32_t smem_u32(const void* p) {
    return (uint32_t)__cvta_generic_to_shared(p);
}
#define CP_ASYNC16(dst, src) \
    asm volatile("cp.async.cg.shared.global [%0], [%1], 16;" :: "r"(dst), "l"(src))
#define CP_COMMIT() asm volatile("cp.async.commit_group;")

#define LDSM4(r0,r1,r2,r3, addr) \
    asm volatile("ldmatrix.sync.aligned.m8n8.x4.shared.b16 {%0,%1,%2,%3}, [%4];" \
        : "=r"(r0),"=r"(r1),"=r"(r2),"=r"(r3) : "r"(addr))
#define LDSM4T(r0,r1,r2,r3, addr) \
    asm volatile("ldmatrix.sync.aligned.m8n8.x4.trans.shared.b16 {%0,%1,%2,%3}, [%4];" \
        : "=r"(r0),"=r"(r1),"=r"(r2),"=r"(r3) : "r"(addr))

__device__ __forceinline__ void mma_bf16(float& c0, float& c1, float& c2, float& c3,
                                         uint32_t a0, uint32_t a1, uint32_t a2, uint32_t a3,
                                         uint32_t b0, uint32_t b1) {
    asm volatile(
        "mma.sync.aligned.m16n8k16.row.col.f32.bf16.bf16.f32 "
        "{%0,%1,%2,%3}, {%4,%5,%6,%7}, {%8,%9}, {%0,%1,%2,%3};"
        : "+f"(c0), "+f"(c1), "+f"(c2), "+f"(c3)
        : "r"(a0), "r"(a1), "r"(a2), "r"(a3), "r"(b0), "r"(b1));
}

// ---------------- GroupNorm stats ----------------
__global__ void gn_stats_kernel(const float* __restrict__ x) {
    int bg = blockIdx.x;
    int b  = bg / NGROUPS;
    int g  = bg % NGROUPS;
    const float* base = x + (size_t)b * HW * C_DIM + g * GSIZE;

    float s = 0.f, ss = 0.f;
    for (int p = threadIdx.x; p < HW; p += blockDim.x) {
        const float4* v4 = (const float4*)(base + (size_t)p * C_DIM);
        #pragma unroll
        for (int j = 0; j < 4; j++) {
            float4 v = v4[j];
            s  += v.x + v.y + v.z + v.w;
            ss += v.x*v.x + v.y*v.y + v.z*v.z + v.w*v.w;
        }
    }
    __shared__ float shs[8], shss[8];
    int lane = threadIdx.x & 31, wid = threadIdx.x >> 5;
    #pragma unroll
    for (int o = 16; o > 0; o >>= 1) {
        s  += __shfl_xor_sync(0xffffffffu, s,  o);
        ss += __shfl_xor_sync(0xffffffffu, ss, o);
    }
    if (lane == 0) { shs[wid] = s; shss[wid] = ss; }
    __syncthreads();
    if (threadIdx.x == 0) {
        float ts = 0.f, tss = 0.f;
        #pragma unroll
        for (int i = 0; i < 8; i++) { ts += shs[i]; tss += shss[i]; }
        const float invn = 1.0f / (float)(HW * GSIZE);
        float mean = ts * invn;
        float var  = tss * invn - mean * mean;
        g_mean[bg] = mean;
        g_rstd[bg] = rsqrtf(var + EPS);
    }
}

// ---------------- GroupNorm apply (writes bf16 hn) ----------------
__global__ void gn_apply_kernel(const float* __restrict__ x,
                                const float* __restrict__ scale,
                                const float* __restrict__ bias) {
    size_t i = (size_t)blockIdx.x * blockDim.x + threadIdx.x;   // float4 index
    int    c4 = (int)(i % (C_DIM / 4));
    size_t t  = i / (C_DIM / 4);
    int    b  = (int)(t / HW);
    int    g  = (c4 * 4) / GSIZE;

    float mean = g_mean[b * NGROUPS + g];
    float rstd = g_rstd[b * NGROUPS + g];
    float4 xv = ((const float4*)x)[i];
    float4 sc = ((const float4*)scale)[c4];
    float4 bi = ((const float4*)bias)[c4];
    float r0 = (xv.x - mean) * rstd * sc.x + bi.x;
    float r1 = (xv.y - mean) * rstd * sc.y + bi.y;
    float r2 = (xv.z - mean) * rstd * sc.z + bi.z;
    float r3 = (xv.w - mean) * rstd * sc.w + bi.w;
    __nv_bfloat162* o = (__nv_bfloat162*)(g_hn + i * 4);
    o[0] = __floats2bfloat162_rn(r0, r1);
    o[1] = __floats2bfloat162_rn(r2, r3);
}

// ---------------- transpose + bf16-round weights ----------------
// w [k][n] fp32 -> g_wt[w_idx] [n][k] bf16
__global__ void prep_weights_kernel(const float* __restrict__ w0,
                                    const float* __restrict__ w1,
                                    const float* __restrict__ w2,
                                    const float* __restrict__ w3) {
    int i = blockIdx.x * blockDim.x + threadIdx.x;  // < 512*512, i = k*512+n
    int k = i >> 9, n = i & 511;
    int o = n * C_DIM + k;
    g_wt[0 * C_DIM * C_DIM + o] = __float2bfloat16_rn(w0[i]);
    g_wt[1 * C_DIM * C_DIM + o] = __float2bfloat16_rn(w1[i]);
    g_wt[2 * C_DIM * C_DIM + o] = __float2bfloat16_rn(w2[i]);
    g_wt[3 * C_DIM * C_DIM + o] = __float2bfloat16_rn(w3[i]);
}

// ---------------- bf16 tensor-core GEMM ----------------
// C = alpha * A @ B' [+ bias] [+ res]
// A: [M,K] bf16 row-major.
// BMODE 0: B stored [N,K] bf16 (n-major rows) -> ldmatrix non-trans
// BMODE 1: B stored [K,N] bf16 (k-major rows) -> ldmatrix trans
// 128x128x32 block tile, 8 warps (2x4), 64x32 warp tile, cp.async double buffer.
template<int BMODE, bool HAS_BIAS, bool HAS_RES, bool OUT_BF16>
__global__ void __launch_bounds__(256, 2)
gemm_bf16(const bf16* __restrict__ A, const bf16* __restrict__ B,
          const float* __restrict__ bias, const float* __restrict__ res,
          void* __restrict__ Cout,
          int M, int N, int K, float alpha,
          size_t sA, size_t sB, size_t sC) {
    constexpr int BM = 128, BN = 128, BK = 32;
    constexpr int ASTR = 40;                        // bf16 units (80B rows)
    constexpr int BSTR = (BMODE == 0) ? 40 : 136;   // 80B or 272B rows
    constexpr int BROWS = (BMODE == 0) ? 128 : 32;
    constexpr int ASTAGE_B = BM * ASTR * 2;         // bytes per stage
    constexpr int BSTAGE_B = BROWS * BSTR * 2;

    __shared__ __align__(16) bf16 As[2][BM * ASTR];
    __shared__ __align__(16) bf16 Bs[2][BROWS * BSTR];

    A += (size_t)blockIdx.z * sA;
    B += (size_t)blockIdx.z * sB;

    const int bm = blockIdx.y * BM;
    const int bn = blockIdx.x * BN;
    const int tid  = threadIdx.x;
    const int lane = tid & 31;
    const int wid  = tid >> 5;
    const int g    = lane >> 2;
    const int t    = lane & 3;
    const int wm   = wid >> 2;      // 0..1  (m offset *64)
    const int wn   = wid & 3;       // 0..3  (n offset *32)

    const uint32_t uAs = smem_u32(&As[0][0]);
    const uint32_t uBs = smem_u32(&Bs[0][0]);

    float acc[4][4][4];
    #pragma unroll
    for (int i = 0; i < 4; i++)
        #pragma unroll
        for (int j = 0; j < 4; j++)
            #pragma unroll
            for (int r = 0; r < 4; r++) acc[i][j][r] = 0.f;

    auto load_stage = [&](int stage, int k0) {
        // A tile: 128 rows x 32 bf16 (64B) = 512 x 16B chunks
        #pragma unroll
        for (int i = 0; i < 2; i++) {
            int c = tid + i * 256;
            int row = c >> 2, kc = c & 3;
            CP_ASYNC16(uAs + stage * ASTAGE_B + (row * ASTR + kc * 8) * 2,
                       A + (size_t)(bm + row) * K + k0 + kc * 8);
        }
        if (BMODE == 0) {
            #pragma unroll
            for (int i = 0; i < 2; i++) {
                int c = tid + i * 256;
                int row = c >> 2, kc = c & 3;
                CP_ASYNC16(uBs + stage * BSTAGE_B + (row * BSTR + kc * 8) * 2,
                           B + (size_t)(bn + row) * K + k0 + kc * 8);
            }
        } else {
            // 32 rows x 128 bf16 (256B) = 512 x 16B chunks
            #pragma unroll
            for (int i = 0; i < 2; i++) {
                int c = tid + i * 256;
                int row = c >> 4, nc = c & 15;
                CP_ASYNC16(uBs + stage * BSTAGE_B + (row * BSTR + nc * 8) * 2,
                           B + (size_t)(k0 + row) * N + bn + nc * 8);
            }
        }
        CP_COMMIT();
    };

    const int nIter = K / BK;
    load_stage(0, 0);

    // precomputed lane pieces
    const int a_row = (lane & 15);          // row within 16-row tile pair
    const int a_kc  = (lane >> 4);          // 0/1 -> k chunk of 8
    const int bnk_r = (lane & 7) + ((lane >> 4) << 3);  // NK: n row
    const int bnk_k = (lane >> 3) & 1;                  // NK: k chunk
    const int bkn_r = (lane & 7) + (((lane >> 3) & 1) << 3);  // KN: k row
    const int bkn_n = (lane >> 4);                            // KN: n chunk

    for (int it = 0; it < nIter; it++) {
        if (it + 1 < nIter) {
            load_stage((it + 1) & 1, (it + 1) * BK);
            asm volatile("cp.async.wait_group 1;");
        } else {
            asm volatile("cp.async.wait_group 0;");
        }
        __syncthreads();

        const int st = it & 1;
        const uint32_t aBase = uAs + st * ASTAGE_B;
        const uint32_t bBase = uBs + st * BSTAGE_B;

        #pragma unroll
        for (int ks = 0; ks < 2; ks++) {
            uint32_t a[4][4];
            #pragma unroll
            for (int mt = 0; mt < 4; mt++) {
                uint32_t addr = aBase +
                    ((wm * 64 + mt * 16 + a_row) * ASTR + ks * 16 + a_kc * 8) * 2;
                LDSM4(a[mt][0], a[mt][1], a[mt][2], a[mt][3], addr);
            }
            uint32_t bq[2][4];
            #pragma unroll
            for (int h = 0; h < 2; h++) {
                if (BMODE == 0) {
                    uint32_t addr = bBase +
                        ((wn * 32 + h * 16 + bnk_r) * BSTR + ks * 16 + bnk_k * 8) * 2;
                    LDSM4(bq[h][0], bq[h][1], bq[h][2], bq[h][3], addr);
                } else {
                    uint32_t addr = bBase +
                        ((ks * 16 + bkn_r) * BSTR + wn * 32 + h * 16 + bkn_n * 8) * 2;
                    LDSM4T(bq[h][0], bq[h][1], bq[h][2], bq[h][3], addr);
                }
            }
            #pragma unroll
            for (int mt = 0; mt < 4; mt++)
                #pragma unroll
                for (int nt = 0; nt < 4; nt++)
                    mma_bf16(acc[mt][nt][0], acc[mt][nt][1], acc[mt][nt][2], acc[mt][nt][3],
                             a[mt][0], a[mt][1], a[mt][2], a[mt][3],
                             bq[nt >> 1][(nt & 1) * 2], bq[nt >> 1][(nt & 1) * 2 + 1]);
        }
        __syncthreads();
    }

    // epilogue
    #pragma unroll
    for (int mt = 0; mt < 4; mt++) {
        int r0 = bm + wm * 64 + mt * 16 + g;
        #pragma unroll
        for (int nt = 0; nt < 4; nt++) {
            int col = bn + wn * 32 + nt * 8 + 2 * t;
            float2 bb = make_float2(0.f, 0.f);
            if (HAS_BIAS) bb = *(const float2*)(bias + col);

            float v0 = acc[mt][nt][0] * alpha + bb.x;
            float v1 = acc[mt][nt][1] * alpha + bb.y;
            float v2 = acc[mt][nt][2] * alpha + bb.x;
            float v3 = acc[mt][nt][3] * alpha + bb.y;
            if (HAS_RES) {
                const float* rp = res + (size_t)blockIdx.z * sC;
                float2 ra = *(const float2*)(rp + (size_t)r0 * N + col);
                float2 rb = *(const float2*)(rp + (size_t)(r0 + 8) * N + col);
                v0 += ra.x; v1 += ra.y; v2 += rb.x; v3 += rb.y;
            }
            if (OUT_BF16) {
                bf16* C = (bf16*)Cout + (size_t)blockIdx.z * sC;
                *(__nv_bfloat162*)(C + (size_t)r0 * N + col)       = __floats2bfloat162_rn(v0, v1);
                *(__nv_bfloat162*)(C + (size_t)(r0 + 8) * N + col) = __floats2bfloat162_rn(v2, v3);
            } else {
                float* C = (float*)Cout + (size_t)blockIdx.z * sC;
                *(float2*)(C + (size_t)r0 * N + col)       = make_float2(v0, v1);
                *(float2*)(C + (size_t)(r0 + 8) * N + col) = make_float2(v2, v3);
            }
        }
    }
}

// ---------------- row softmax over 4096 keys: fp32 in, bf16 out ----------------
__global__ void softmax_rows_kernel(const float* __restrict__ S, bf16* __restrict__ P) {
    const float* p = S + (size_t)blockIdx.x * HW;
    bf16* po = P + (size_t)blockIdx.x * HW;
    const int tid = threadIdx.x;
    const int lane = tid & 31, wid = tid >> 5;
    __shared__ float shm[8], shs[8];
    __shared__ float bmax, bsum;

    float v[16];
    float mx = -CUDART_INF_F;
    #pragma unroll
    for (int i = 0; i < 4; i++) {
        float4 t = *(const float4*)(p + i * 1024 + tid * 4);
        v[i * 4 + 0] = t.x; v[i * 4 + 1] = t.y;
        v[i * 4 + 2] = t.z; v[i * 4 + 3] = t.w;
        mx = fmaxf(mx, fmaxf(fmaxf(t.x, t.y), fmaxf(t.z, t.w)));
    }
    #pragma unroll
    for (int o = 16; o > 0; o >>= 1) mx = fmaxf(mx, __shfl_xor_sync(0xffffffffu, mx, o));
    if (lane == 0) shm[wid] = mx;
    __syncthreads();
    if (tid == 0) {
        float t = shm[0];
        #pragma unroll
        for (int i = 1; i < 8; i++) t = fmaxf(t, shm[i]);
        bmax = t;
    }
    __syncthreads();
    mx = bmax;

    float sum = 0.f;
    #pragma unroll
    for (int i = 0; i < 16; i++) { v[i] = __expf(v[i] - mx); sum += v[i]; }
    #pragma unroll
    for (int o = 16; o > 0; o >>= 1) sum += __shfl_xor_sync(0xffffffffu, sum, o);
    if (lane == 0) shs[wid] = sum;
    __syncthreads();
    if (tid == 0) {
        float t = 0.f;
        #pragma unroll
        for (int i = 0; i < 8; i++) t += shs[i];
        bsum = 1.0f / t;
    }
    __syncthreads();
    const float inv = bsum;

    #pragma unroll
    for (int i = 0; i < 4; i++) {
        __nv_bfloat162* o2 = (__nv_bfloat162*)(po + i * 1024 + tid * 4);
        o2[0] = __floats2bfloat162_rn(v[i * 4 + 0] * inv, v[i * 4 + 1] * inv);
        o2[1] = __floats2bfloat162_rn(v[i * 4 + 2] * inv, v[i * 4 + 3] * inv);
    }
}

// ---------------- launch ----------------
extern "C" void kernel_launch(void* const* d_in, const int* in_sizes, int n_in,
                              void* d_out, int out_size) {
    const float* x        = (const float*)d_in[0];
    const float* gn_scale = (const float*)d_in[1];
    const float* gn_bias  = (const float*)d_in[2];
    const float* wq = (const float*)d_in[3];  const float* bq = (const float*)d_in[4];
    const float* wk = (const float*)d_in[5];  const float* bk = (const float*)d_in[6];
    const float* wv = (const float*)d_in[7];  const float* bv = (const float*)d_in[8];
    const float* wo = (const float*)d_in[9];  const float* bo = (const float*)d_in[10];
    float* out = (float*)d_out;

    bf16 *hn, *q, *kb, *v, *p, *o, *wt;
    float *s;
    cudaGetSymbolAddress((void**)&hn, g_hn);
    cudaGetSymbolAddress((void**)&q,  g_q);
    cudaGetSymbolAddress((void**)&kb, g_k);
    cudaGetSymbolAddress((void**)&v,  g_v);
    cudaGetSymbolAddress((void**)&s,  g_s);
    cudaGetSymbolAddress((void**)&p,  g_p);
    cudaGetSymbolAddress((void**)&o,  g_o);
    cudaGetSymbolAddress((void**)&wt, g_wt);
    const bf16* wqt = wt + 0 * C_DIM * C_DIM;
    const bf16* wkt = wt + 1 * C_DIM * C_DIM;
    const bf16* wvt = wt + 2 * C_DIM * C_DIM;
    const bf16* wot = wt + 3 * C_DIM * C_DIM;

    // 1) GroupNorm + weight prep
    gn_stats_kernel<<<BATCH * NGROUPS, 256>>>(x);
    gn_apply_kernel<<<(NTOK * C_DIM / 4) / 256, 256>>>(x, gn_scale, gn_bias);
    prep_weights_kernel<<<(C_DIM * C_DIM) / 256, 256>>>(wq, wk, wv, wo);

    dim3 blk(256);
    // 2) QKV projections: bf16 out
    dim3 gproj(C_DIM / 128, NTOK / 128, 1);
    gemm_bf16<0, true, false, true><<<gproj, blk>>>(hn, wqt, bq, nullptr, q,
        NTOK, C_DIM, C_DIM, 1.0f, 0, 0, 0);
    gemm_bf16<0, true, false, true><<<gproj, blk>>>(hn, wkt, bk, nullptr, kb,
        NTOK, C_DIM, C_DIM, 1.0f, 0, 0, 0);
    gemm_bf16<0, true, false, true><<<gproj, blk>>>(hn, wvt, bv, nullptr, v,
        NTOK, C_DIM, C_DIM, 1.0f, 0, 0, 0);

    // 3) S = (Q @ K^T) * c^-0.5, batched; fp32 out
    dim3 gs(HW / 128, HW / 128, BATCH);
    gemm_bf16<0, false, false, false><<<gs, blk>>>(q, kb, nullptr, nullptr, s,
        HW, HW, C_DIM, SM_SCALE,
        (size_t)HW * C_DIM, (size_t)HW * C_DIM, (size_t)HW * HW);

    // 4) softmax: fp32 -> bf16
    softmax_rows_kernel<<<NTOK, 256>>>(s, p);

    // 5) O = P @ V, batched; V is [k][n] -> BMODE 1; bf16 out
    dim3 gpv(C_DIM / 128, HW / 128, BATCH);
    gemm_bf16<1, false, false, true><<<gpv, blk>>>(p, v, nullptr, nullptr, o,
        HW, C_DIM, HW, 1.0f,
        (size_t)HW * HW, (size_t)HW * C_DIM, (size_t)HW * C_DIM);

    // 6) out = x + O @ wo + bo ; fp32 out
    gemm_bf16<0, true, true, false><<<gproj, blk>>>(o, wot, bo, x, out,
        NTOK, C_DIM, C_DIM, 1.0f, 0, 0, 0);
}

// round 5
// speedup vs baseline: 6.4717x; 1.0371x over previous
#include <cuda_runtime.h>
#include <cuda_bf16.h>
#include <math_constants.h>
#include <cstdint>

// ---------------- problem constants ----------------
#define C_DIM   512
#define NGROUPS 32
#define GSIZE   16
#define BATCH   4
#define HW      4096
#define NTOK    16384
#define EPS     1e-6f
#define SM_SCALE 0.04419417382415922f   // 512^-0.5
#define QKV_N   1536

typedef __nv_bfloat16 bf16;

// ---------------- device scratch ----------------
__device__ float g_mean[BATCH * NGROUPS];
__device__ float g_rstd[BATCH * NGROUPS];
__device__ bf16  g_hn  [NTOK * C_DIM];
__device__ bf16  g_qkv [(size_t)NTOK * QKV_N];        // 48 MB
__device__ bf16  g_s   [(size_t)BATCH * HW * HW];     // 128 MB (scores -> probs in place)
__device__ bf16  g_o   [NTOK * C_DIM];
__device__ bf16  g_wqkv[QKV_N * C_DIM];               // [n][k] bf16
__device__ bf16  g_wo  [C_DIM * C_DIM];               // [n][k] bf16
__device__ float g_bqkv[QKV_N];

// ---------------- helpers ----------------
__device__ __forceinline__ uint32_t smem_u32(const void* p) {
    return (uint32_t)__cvta_generic_to_shared(p);
}
#define CP_ASYNC16(dst, src) \
    asm volatile("cp.async.cg.shared.global [%0], [%1], 16;" :: "r"(dst), "l"(src))
#define CP_COMMIT() asm volatile("cp.async.commit_group;")

#define LDSM4(r0,r1,r2,r3, addr) \
    asm volatile("ldmatrix.sync.aligned.m8n8.x4.shared.b16 {%0,%1,%2,%3}, [%4];" \
        : "=r"(r0),"=r"(r1),"=r"(r2),"=r"(r3) : "r"(addr))
#define LDSM4T(r0,r1,r2,r3, addr) \
    asm volatile("ldmatrix.sync.aligned.m8n8.x4.trans.shared.b16 {%0,%1,%2,%3}, [%4];" \
        : "=r"(r0),"=r"(r1),"=r"(r2),"=r"(r3) : "r"(addr))

__device__ __forceinline__ void mma_bf16(float& c0, float& c1, float& c2, float& c3,
                                         uint32_t a0, uint32_t a1, uint32_t a2, uint32_t a3,
                                         uint32_t b0, uint32_t b1) {
    asm volatile(
        "mma.sync.aligned.m16n8k16.row.col.f32.bf16.bf16.f32 "
        "{%0,%1,%2,%3}, {%4,%5,%6,%7}, {%8,%9}, {%0,%1,%2,%3};"
        : "+f"(c0), "+f"(c1), "+f"(c2), "+f"(c3)
        : "r"(a0), "r"(a1), "r"(a2), "r"(a3), "r"(b0), "r"(b1));
}

// ---------------- GroupNorm stats ----------------
__global__ void gn_stats_kernel(const float* __restrict__ x) {
    int bg = blockIdx.x;
    int b  = bg / NGROUPS;
    int g  = bg % NGROUPS;
    const float* base = x + (size_t)b * HW * C_DIM + g * GSIZE;

    float s = 0.f, ss = 0.f;
    for (int p = threadIdx.x; p < HW; p += blockDim.x) {
        const float4* v4 = (const float4*)(base + (size_t)p * C_DIM);
        #pragma unroll
        for (int j = 0; j < 4; j++) {
            float4 v = v4[j];
            s  += v.x + v.y + v.z + v.w;
            ss += v.x*v.x + v.y*v.y + v.z*v.z + v.w*v.w;
        }
    }
    __shared__ float shs[8], shss[8];
    int lane = threadIdx.x & 31, wid = threadIdx.x >> 5;
    #pragma unroll
    for (int o = 16; o > 0; o >>= 1) {
        s  += __shfl_xor_sync(0xffffffffu, s,  o);
        ss += __shfl_xor_sync(0xffffffffu, ss, o);
    }
    if (lane == 0) { shs[wid] = s; shss[wid] = ss; }
    __syncthreads();
    if (threadIdx.x == 0) {
        float ts = 0.f, tss = 0.f;
        #pragma unroll
        for (int i = 0; i < 8; i++) { ts += shs[i]; tss += shss[i]; }
        const float invn = 1.0f / (float)(HW * GSIZE);
        float mean = ts * invn;
        float var  = tss * invn - mean * mean;
        g_mean[bg] = mean;
        g_rstd[bg] = rsqrtf(var + EPS);
    }
}

// ---------------- GroupNorm apply (writes bf16 hn) ----------------
__global__ void gn_apply_kernel(const float* __restrict__ x,
                                const float* __restrict__ scale,
                                const float* __restrict__ bias) {
    size_t i = (size_t)blockIdx.x * blockDim.x + threadIdx.x;   // float4 index
    int    c4 = (int)(i % (C_DIM / 4));
    size_t t  = i / (C_DIM / 4);
    int    b  = (int)(t / HW);
    int    g  = (c4 * 4) / GSIZE;

    float mean = g_mean[b * NGROUPS + g];
    float rstd = g_rstd[b * NGROUPS + g];
    float4 xv = ((const float4*)x)[i];
    float4 sc = ((const float4*)scale)[c4];
    float4 bi = ((const float4*)bias)[c4];
    float r0 = (xv.x - mean) * rstd * sc.x + bi.x;
    float r1 = (xv.y - mean) * rstd * sc.y + bi.y;
    float r2 = (xv.z - mean) * rstd * sc.z + bi.z;
    float r3 = (xv.w - mean) * rstd * sc.w + bi.w;
    __nv_bfloat162* o = (__nv_bfloat162*)(g_hn + i * 4);
    o[0] = __floats2bfloat162_rn(r0, r1);
    o[1] = __floats2bfloat162_rn(r2, r3);
}

// ---------------- weight prep: transpose + bf16 + concat ----------------
__global__ void prep_weights_kernel(const float* __restrict__ wq,
                                    const float* __restrict__ wk,
                                    const float* __restrict__ wv,
                                    const float* __restrict__ wo,
                                    const float* __restrict__ bq,
                                    const float* __restrict__ bk,
                                    const float* __restrict__ bv) {
    int i = blockIdx.x * blockDim.x + threadIdx.x;  // < 512*512, i = k*512+n
    int k = i >> 9, n = i & 511;
    g_wqkv[(n)        * C_DIM + k] = __float2bfloat16_rn(wq[i]);
    g_wqkv[(n + 512)  * C_DIM + k] = __float2bfloat16_rn(wk[i]);
    g_wqkv[(n + 1024) * C_DIM + k] = __float2bfloat16_rn(wv[i]);
    g_wo  [n * C_DIM + k]          = __float2bfloat16_rn(wo[i]);
    if (i < 512) {
        g_bqkv[i]        = bq[i];
        g_bqkv[i + 512]  = bk[i];
        g_bqkv[i + 1024] = bv[i];
    }
}

// ---------------- bf16 tensor-core GEMM (3-stage cp.async) ----------------
// C = alpha * A @ B' [+ bias] [+ res]
// A: [M,K] bf16, row stride lda.
// BMODE 0: B stored [N,K] (row stride ldb) -> ldmatrix non-trans
// BMODE 1: B stored [K,N] (row stride ldb) -> ldmatrix trans
// 128x128x32 block tile, 8 warps (2x4), 64x32 warp tile.
template<int BMODE, bool HAS_BIAS, bool HAS_RES, bool OUT_BF16>
__global__ void __launch_bounds__(256, 2)
gemm_bf16(const bf16* __restrict__ A, const bf16* __restrict__ B,
          const float* __restrict__ bias, const float* __restrict__ res,
          void* __restrict__ Cout,
          int M, int N, int K, int lda, int ldb, float alpha,
          size_t sA, size_t sB, size_t sC) {
    constexpr int BM = 128, BN = 128, BK = 32;
    constexpr int NSTAGE = 3;
    constexpr int ASTR = 40;                        // bf16 units (80B rows)
    constexpr int BSTR = (BMODE == 0) ? 40 : 136;
    constexpr int BROWS = (BMODE == 0) ? 128 : 32;
    constexpr int ASTAGE_B = BM * ASTR * 2;
    constexpr int BSTAGE_B = BROWS * BSTR * 2;

    __shared__ __align__(16) bf16 As[NSTAGE][BM * ASTR];
    __shared__ __align__(16) bf16 Bs[NSTAGE][BROWS * BSTR];

    A += (size_t)blockIdx.z * sA;
    B += (size_t)blockIdx.z * sB;

    const int bm = blockIdx.y * BM;
    const int bn = blockIdx.x * BN;
    const int tid  = threadIdx.x;
    const int lane = tid & 31;
    const int wid  = tid >> 5;
    const int g    = lane >> 2;
    const int t    = lane & 3;
    const int wm   = wid >> 2;
    const int wn   = wid & 3;

    const uint32_t uAs = smem_u32(&As[0][0]);
    const uint32_t uBs = smem_u32(&Bs[0][0]);

    float acc[4][4][4];
    #pragma unroll
    for (int i = 0; i < 4; i++)
        #pragma unroll
        for (int j = 0; j < 4; j++)
            #pragma unroll
            for (int r = 0; r < 4; r++) acc[i][j][r] = 0.f;

    auto load_stage = [&](int stage, int k0) {
        #pragma unroll
        for (int i = 0; i < 2; i++) {
            int c = tid + i * 256;
            int row = c >> 2, kc = c & 3;
            CP_ASYNC16(uAs + stage * ASTAGE_B + (row * ASTR + kc * 8) * 2,
                       A + (size_t)(bm + row) * lda + k0 + kc * 8);
        }
        if (BMODE == 0) {
            #pragma unroll
            for (int i = 0; i < 2; i++) {
                int c = tid + i * 256;
                int row = c >> 2, kc = c & 3;
                CP_ASYNC16(uBs + stage * BSTAGE_B + (row * BSTR + kc * 8) * 2,
                           B + (size_t)(bn + row) * ldb + k0 + kc * 8);
            }
        } else {
            #pragma unroll
            for (int i = 0; i < 2; i++) {
                int c = tid + i * 256;
                int row = c >> 4, nc = c & 15;
                CP_ASYNC16(uBs + stage * BSTAGE_B + (row * BSTR + nc * 8) * 2,
                           B + (size_t)(k0 + row) * ldb + bn + nc * 8);
            }
        }
        CP_COMMIT();
    };

    const int nIter = K / BK;
    load_stage(0, 0);
    if (nIter > 1) load_stage(1, BK);

    const int a_row = (lane & 15);
    const int a_kc  = (lane >> 4);
    const int bnk_r = (lane & 7) + ((lane >> 4) << 3);
    const int bnk_k = (lane >> 3) & 1;
    const int bkn_r = (lane & 7) + (((lane >> 3) & 1) << 3);
    const int bkn_n = (lane >> 4);

    int stage = 0;
    for (int it = 0; it < nIter; it++) {
        if (it + 1 < nIter) {
            asm volatile("cp.async.wait_group 1;");
        } else {
            asm volatile("cp.async.wait_group 0;");
        }
        __syncthreads();

        if (it + 2 < nIter) {
            int ls = stage + 2; if (ls >= NSTAGE) ls -= NSTAGE;
            load_stage(ls, (it + 2) * BK);
        }

        const uint32_t aBase = uAs + stage * ASTAGE_B;
        const uint32_t bBase = uBs + stage * BSTAGE_B;

        #pragma unroll
        for (int ks = 0; ks < 2; ks++) {
            uint32_t a[4][4];
            #pragma unroll
            for (int mt = 0; mt < 4; mt++) {
                uint32_t addr = aBase +
                    ((wm * 64 + mt * 16 + a_row) * ASTR + ks * 16 + a_kc * 8) * 2;
                LDSM4(a[mt][0], a[mt][1], a[mt][2], a[mt][3], addr);
            }
            uint32_t bq[2][4];
            #pragma unroll
            for (int h = 0; h < 2; h++) {
                if (BMODE == 0) {
                    uint32_t addr = bBase +
                        ((wn * 32 + h * 16 + bnk_r) * BSTR + ks * 16 + bnk_k * 8) * 2;
                    LDSM4(bq[h][0], bq[h][1], bq[h][2], bq[h][3], addr);
                } else {
                    uint32_t addr = bBase +
                        ((ks * 16 + bkn_r) * BSTR + wn * 32 + h * 16 + bkn_n * 8) * 2;
                    LDSM4T(bq[h][0], bq[h][1], bq[h][2], bq[h][3], addr);
                }
            }
            #pragma unroll
            for (int mt = 0; mt < 4; mt++)
                #pragma unroll
                for (int nt = 0; nt < 4; nt++)
                    mma_bf16(acc[mt][nt][0], acc[mt][nt][1], acc[mt][nt][2], acc[mt][nt][3],
                             a[mt][0], a[mt][1], a[mt][2], a[mt][3],
                             bq[nt >> 1][(nt & 1) * 2], bq[nt >> 1][(nt & 1) * 2 + 1]);
        }
        __syncthreads();
        stage++; if (stage >= NSTAGE) stage = 0;
    }

    // epilogue
    #pragma unroll
    for (int mt = 0; mt < 4; mt++) {
        int r0 = bm + wm * 64 + mt * 16 + g;
        #pragma unroll
        for (int nt = 0; nt < 4; nt++) {
            int col = bn + wn * 32 + nt * 8 + 2 * t;
            float2 bb = make_float2(0.f, 0.f);
            if (HAS_BIAS) bb = *(const float2*)(bias + col);

            float v0 = acc[mt][nt][0] * alpha + bb.x;
            float v1 = acc[mt][nt][1] * alpha + bb.y;
            float v2 = acc[mt][nt][2] * alpha + bb.x;
            float v3 = acc[mt][nt][3] * alpha + bb.y;
            if (HAS_RES) {
                const float* rp = res + (size_t)blockIdx.z * sC;
                float2 ra = *(const float2*)(rp + (size_t)r0 * N + col);
                float2 rb = *(const float2*)(rp + (size_t)(r0 + 8) * N + col);
                v0 += ra.x; v1 += ra.y; v2 += rb.x; v3 += rb.y;
            }
            if (OUT_BF16) {
                bf16* C = (bf16*)Cout + (size_t)blockIdx.z * sC;
                *(__nv_bfloat162*)(C + (size_t)r0 * N + col)       = __floats2bfloat162_rn(v0, v1);
                *(__nv_bfloat162*)(C + (size_t)(r0 + 8) * N + col) = __floats2bfloat162_rn(v2, v3);
            } else {
                float* C = (float*)Cout + (size_t)blockIdx.z * sC;
                *(float2*)(C + (size_t)r0 * N + col)       = make_float2(v0, v1);
                *(float2*)(C + (size_t)(r0 + 8) * N + col) = make_float2(v2, v3);
            }
        }
    }
}

// ---------------- row softmax over 4096 keys: bf16 in-place ----------------
__global__ void softmax_rows_kernel(bf16* __restrict__ S) {
    bf16* p = S + (size_t)blockIdx.x * HW;
    const int tid = threadIdx.x;
    const int lane = tid & 31, wid = tid >> 5;
    __shared__ float shm[8], shs[8];
    __shared__ float bmax, bsum;

    // 16 bf16 per thread = 2x 16B loads
    float v[16];
    float mx = -CUDART_INF_F;
    #pragma unroll
    for (int i = 0; i < 2; i++) {
        uint4 raw = *(const uint4*)(p + i * 2048 + tid * 8);
        const __nv_bfloat162* h2 = (const __nv_bfloat162*)&raw;
        #pragma unroll
        for (int j = 0; j < 4; j++) {
            float2 f = __bfloat1622float2(h2[j]);
            v[i * 8 + j * 2 + 0] = f.x;
            v[i * 8 + j * 2 + 1] = f.y;
            mx = fmaxf(mx, fmaxf(f.x, f.y));
        }
    }
    #pragma unroll
    for (int o = 16; o > 0; o >>= 1) mx = fmaxf(mx, __shfl_xor_sync(0xffffffffu, mx, o));
    if (lane == 0) shm[wid] = mx;
    __syncthreads();
    if (tid == 0) {
        float t = shm[0];
        #pragma unroll
        for (int i = 1; i < 8; i++) t = fmaxf(t, shm[i]);
        bmax = t;
    }
    __syncthreads();
    mx = bmax;

    float sum = 0.f;
    #pragma unroll
    for (int i = 0; i < 16; i++) { v[i] = __expf(v[i] - mx); sum += v[i]; }
    #pragma unroll
    for (int o = 16; o > 0; o >>= 1) sum += __shfl_xor_sync(0xffffffffu, sum, o);
    if (lane == 0) shs[wid] = sum;
    __syncthreads();
    if (tid == 0) {
        float t = 0.f;
        #pragma unroll
        for (int i = 0; i < 8; i++) t += shs[i];
        bsum = 1.0f / t;
    }
    __syncthreads();
    const float inv = bsum;

    #pragma unroll
    for (int i = 0; i < 2; i++) {
        uint4 raw;
        __nv_bfloat162* h2 = (__nv_bfloat162*)&raw;
        #pragma unroll
        for (int j = 0; j < 4; j++)
            h2[j] = __floats2bfloat162_rn(v[i * 8 + j * 2 + 0] * inv,
                                          v[i * 8 + j * 2 + 1] * inv);
        *(uint4*)(p + i * 2048 + tid * 8) = raw;
    }
}

// ---------------- launch ----------------
extern "C" void kernel_launch(void* const* d_in, const int* in_sizes, int n_in,
                              void* d_out, int out_size) {
    const float* x        = (const float*)d_in[0];
    const float* gn_scale = (const float*)d_in[1];
    const float* gn_bias  = (const float*)d_in[2];
    const float* wq = (const float*)d_in[3];  const float* bq = (const float*)d_in[4];
    const float* wk = (const float*)d_in[5];  const float* bk = (const float*)d_in[6];
    const float* wv = (const float*)d_in[7];  const float* bv = (const float*)d_in[8];
    const float* wo = (const float*)d_in[9];  const float* bo = (const float*)d_in[10];
    float* out = (float*)d_out;

    bf16 *hn, *qkv, *s, *o, *wqkvp, *wop;
    float *bqkvp;
    cudaGetSymbolAddress((void**)&hn,    g_hn);
    cudaGetSymbolAddress((void**)&qkv,   g_qkv);
    cudaGetSymbolAddress((void**)&s,     g_s);
    cudaGetSymbolAddress((void**)&o,     g_o);
    cudaGetSymbolAddress((void**)&wqkvp, g_wqkv);
    cudaGetSymbolAddress((void**)&wop,   g_wo);
    cudaGetSymbolAddress((void**)&bqkvp, g_bqkv);

    // 1) GroupNorm + weight prep
    gn_stats_kernel<<<BATCH * NGROUPS, 256>>>(x);
    gn_apply_kernel<<<(NTOK * C_DIM / 4) / 256, 256>>>(x, gn_scale, gn_bias);
    prep_weights_kernel<<<(C_DIM * C_DIM) / 256, 256>>>(wq, wk, wv, wo, bq, bk, bv);

    dim3 blk(256);
    // 2) fused QKV projection: [16384,512] @ [512,1536] -> g_qkv bf16
    dim3 gqkv(QKV_N / 128, NTOK / 128, 1);
    gemm_bf16<0, true, false, true><<<gqkv, blk>>>(hn, wqkvp, bqkvp, nullptr, qkv,
        NTOK, QKV_N, C_DIM, C_DIM, C_DIM, 1.0f, 0, 0, 0);

    const bf16* qp = qkv;
    const bf16* kp = qkv + 512;
    const bf16* vp = qkv + 1024;

    // 3) S = (Q @ K^T) * c^-0.5, batched; bf16 out
    dim3 gs(HW / 128, HW / 128, BATCH);
    gemm_bf16<0, false, false, true><<<gs, blk>>>(qp, kp, nullptr, nullptr, s,
        HW, HW, C_DIM, QKV_N, QKV_N, SM_SCALE,
        (size_t)HW * QKV_N, (size_t)HW * QKV_N, (size_t)HW * HW);

    // 4) softmax in place (bf16)
    softmax_rows_kernel<<<NTOK, 256>>>(s);

    // 5) O = P @ V, batched; V rows are tokens with stride QKV_N -> BMODE 1
    dim3 gpv(C_DIM / 128, HW / 128, BATCH);
    gemm_bf16<1, false, false, true><<<gpv, blk>>>(s, vp, nullptr, nullptr, o,
        HW, C_DIM, HW, HW, QKV_N, 1.0f,
        (size_t)HW * HW, (size_t)HW * QKV_N, (size_t)HW * C_DIM);

    // 6) out = x + O @ wo + bo ; fp32 out
    dim3 gproj(C_DIM / 128, NTOK / 128, 1);
    gemm_bf16<0, true, true, false><<<gproj, blk>>>(o, wop, bo, x, out,
        NTOK, C_DIM, C_DIM, C_DIM, C_DIM, 1.0f, 0, 0, 0);
}

// round 6
// speedup vs baseline: 6.4763x; 1.0007x over previous
#include <cuda_runtime.h>
#include <cuda_bf16.h>
#include <math_constants.h>
#include <cstdint>

// ---------------- problem constants ----------------
#define C_DIM   512
#define NGROUPS 32
#define GSIZE   16
#define BATCH   4
#define HW      4096
#define NTOK    16384
#define EPS     1e-6f
#define SM_SCALE 0.04419417382415922f   // 512^-0.5
#define QKV_N   1536

typedef __nv_bfloat16 bf16;

// ---------------- device scratch ----------------
__device__ float g_mean[BATCH * NGROUPS];
__device__ float g_rstd[BATCH * NGROUPS];
__device__ bf16  g_hn  [NTOK * C_DIM];
__device__ bf16  g_qkv [(size_t)NTOK * QKV_N];        // 48 MB
__device__ bf16  g_s   [(size_t)BATCH * HW * HW];     // 128 MB (scores -> probs in place)
__device__ bf16  g_o   [NTOK * C_DIM];
__device__ bf16  g_wqkv[QKV_N * C_DIM];               // [n][k] bf16
__device__ bf16  g_wo  [C_DIM * C_DIM];               // [n][k] bf16
__device__ float g_bqkv[QKV_N];

// ---------------- helpers ----------------
__device__ __forceinline__ uint32_t smem_u32(const void* p) {
    return (uint32_t)__cvta_generic_to_shared(p);
}
#define CP_ASYNC16(dst, src) \
    asm volatile("cp.async.cg.shared.global [%0], [%1], 16;" :: "r"(dst), "l"(src))
#define CP_COMMIT() asm volatile("cp.async.commit_group;")

#define LDSM4(r0,r1,r2,r3, addr) \
    asm volatile("ldmatrix.sync.aligned.m8n8.x4.shared.b16 {%0,%1,%2,%3}, [%4];" \
        : "=r"(r0),"=r"(r1),"=r"(r2),"=r"(r3) : "r"(addr))
#define LDSM4T(r0,r1,r2,r3, addr) \
    asm volatile("ldmatrix.sync.aligned.m8n8.x4.trans.shared.b16 {%0,%1,%2,%3}, [%4];" \
        : "=r"(r0),"=r"(r1),"=r"(r2),"=r"(r3) : "r"(addr))

__device__ __forceinline__ void mma_bf16(float& c0, float& c1, float& c2, float& c3,
                                         uint32_t a0, uint32_t a1, uint32_t a2, uint32_t a3,
                                         uint32_t b0, uint32_t b1) {
    asm volatile(
        "mma.sync.aligned.m16n8k16.row.col.f32.bf16.bf16.f32 "
        "{%0,%1,%2,%3}, {%4,%5,%6,%7}, {%8,%9}, {%0,%1,%2,%3};"
        : "+f"(c0), "+f"(c1), "+f"(c2), "+f"(c3)
        : "r"(a0), "r"(a1), "r"(a2), "r"(a3), "r"(b0), "r"(b1));
}

// ---------------- GroupNorm stats ----------------
__global__ void gn_stats_kernel(const float* __restrict__ x) {
    int bg = blockIdx.x;
    int b  = bg / NGROUPS;
    int g  = bg % NGROUPS;
    const float* base = x + (size_t)b * HW * C_DIM + g * GSIZE;

    float s = 0.f, ss = 0.f;
    for (int p = threadIdx.x; p < HW; p += blockDim.x) {
        const float4* v4 = (const float4*)(base + (size_t)p * C_DIM);
        #pragma unroll
        for (int j = 0; j < 4; j++) {
            float4 v = v4[j];
            s  += v.x + v.y + v.z + v.w;
            ss += v.x*v.x + v.y*v.y + v.z*v.z + v.w*v.w;
        }
    }
    __shared__ float shs[8], shss[8];
    int lane = threadIdx.x & 31, wid = threadIdx.x >> 5;
    #pragma unroll
    for (int o = 16; o > 0; o >>= 1) {
        s  += __shfl_xor_sync(0xffffffffu, s,  o);
        ss += __shfl_xor_sync(0xffffffffu, ss, o);
    }
    if (lane == 0) { shs[wid] = s; shss[wid] = ss; }
    __syncthreads();
    if (threadIdx.x == 0) {
        float ts = 0.f, tss = 0.f;
        #pragma unroll
        for (int i = 0; i < 8; i++) { ts += shs[i]; tss += shss[i]; }
        const float invn = 1.0f / (float)(HW * GSIZE);
        float mean = ts * invn;
        float var  = tss * invn - mean * mean;
        g_mean[bg] = mean;
        g_rstd[bg] = rsqrtf(var + EPS);
    }
}

// ---------------- GroupNorm apply (writes bf16 hn) ----------------
__global__ void gn_apply_kernel(const float* __restrict__ x,
                                const float* __restrict__ scale,
                                const float* __restrict__ bias) {
    size_t i = (size_t)blockIdx.x * blockDim.x + threadIdx.x;   // float4 index
    int    c4 = (int)(i % (C_DIM / 4));
    size_t t  = i / (C_DIM / 4);
    int    b  = (int)(t / HW);
    int    g  = (c4 * 4) / GSIZE;

    float mean = g_mean[b * NGROUPS + g];
    float rstd = g_rstd[b * NGROUPS + g];
    float4 xv = ((const float4*)x)[i];
    float4 sc = ((const float4*)scale)[c4];
    float4 bi = ((const float4*)bias)[c4];
    float r0 = (xv.x - mean) * rstd * sc.x + bi.x;
    float r1 = (xv.y - mean) * rstd * sc.y + bi.y;
    float r2 = (xv.z - mean) * rstd * sc.z + bi.z;
    float r3 = (xv.w - mean) * rstd * sc.w + bi.w;
    __nv_bfloat162* o = (__nv_bfloat162*)(g_hn + i * 4);
    o[0] = __floats2bfloat162_rn(r0, r1);
    o[1] = __floats2bfloat162_rn(r2, r3);
}

// ---------------- weight prep: transpose + bf16 + concat ----------------
__global__ void prep_weights_kernel(const float* __restrict__ wq,
                                    const float* __restrict__ wk,
                                    const float* __restrict__ wv,
                                    const float* __restrict__ wo,
                                    const float* __restrict__ bq,
                                    const float* __restrict__ bk,
                                    const float* __restrict__ bv) {
    int i = blockIdx.x * blockDim.x + threadIdx.x;  // < 512*512, i = k*512+n
    int k = i >> 9, n = i & 511;
    g_wqkv[(n)        * C_DIM + k] = __float2bfloat16_rn(wq[i]);
    g_wqkv[(n + 512)  * C_DIM + k] = __float2bfloat16_rn(wk[i]);
    g_wqkv[(n + 1024) * C_DIM + k] = __float2bfloat16_rn(wv[i]);
    g_wo  [n * C_DIM + k]          = __float2bfloat16_rn(wo[i]);
    if (i < 512) {
        g_bqkv[i]        = bq[i];
        g_bqkv[i + 512]  = bk[i];
        g_bqkv[i + 1024] = bv[i];
    }
}

// ---------------- bf16 tensor-core GEMM (3-stage cp.async) ----------------
// C = alpha * A @ B' [+ bias] [+ res]
// A: [M,K] bf16, row stride lda.
// BMODE 0: B stored [N,K] (row stride ldb) -> ldmatrix non-trans
// BMODE 1: B stored [K,N] (row stride ldb) -> ldmatrix trans
// 128x128x32 block tile, 8 warps (2x4), 64x32 warp tile.
template<int BMODE, bool HAS_BIAS, bool HAS_RES, bool OUT_BF16>
__global__ void __launch_bounds__(256, 2)
gemm_bf16(const bf16* __restrict__ A, const bf16* __restrict__ B,
          const float* __restrict__ bias, const float* __restrict__ res,
          void* __restrict__ Cout,
          int M, int N, int K, int lda, int ldb, float alpha,
          size_t sA, size_t sB, size_t sC) {
    constexpr int BM = 128, BN = 128, BK = 32;
    constexpr int NSTAGE = 3;
    constexpr int ASTR = 40;                        // bf16 units (80B rows)
    constexpr int BSTR = (BMODE == 0) ? 40 : 136;
    constexpr int BROWS = (BMODE == 0) ? 128 : 32;
    constexpr int ASTAGE_B = BM * ASTR * 2;
    constexpr int BSTAGE_B = BROWS * BSTR * 2;

    __shared__ __align__(16) bf16 As[NSTAGE][BM * ASTR];
    __shared__ __align__(16) bf16 Bs[NSTAGE][BROWS * BSTR];

    A += (size_t)blockIdx.z * sA;
    B += (size_t)blockIdx.z * sB;

    const int bm = blockIdx.y * BM;
    const int bn = blockIdx.x * BN;
    const int tid  = threadIdx.x;
    const int lane = tid & 31;
    const int wid  = tid >> 5;
    const int g    = lane >> 2;
    const int t    = lane & 3;
    const int wm   = wid >> 2;
    const int wn   = wid & 3;

    const uint32_t uAs = smem_u32(&As[0][0]);
    const uint32_t uBs = smem_u32(&Bs[0][0]);

    float acc[4][4][4];
    #pragma unroll
    for (int i = 0; i < 4; i++)
        #pragma unroll
        for (int j = 0; j < 4; j++)
            #pragma unroll
            for (int r = 0; r < 4; r++) acc[i][j][r] = 0.f;

    auto load_stage = [&](int stage, int k0) {
        #pragma unroll
        for (int i = 0; i < 2; i++) {
            int c = tid + i * 256;
            int row = c >> 2, kc = c & 3;
            CP_ASYNC16(uAs + stage * ASTAGE_B + (row * ASTR + kc * 8) * 2,
                       A + (size_t)(bm + row) * lda + k0 + kc * 8);
        }
        if (BMODE == 0) {
            #pragma unroll
            for (int i = 0; i < 2; i++) {
                int c = tid + i * 256;
                int row = c >> 2, kc = c & 3;
                CP_ASYNC16(uBs + stage * BSTAGE_B + (row * BSTR + kc * 8) * 2,
                           B + (size_t)(bn + row) * ldb + k0 + kc * 8);
            }
        } else {
            #pragma unroll
            for (int i = 0; i < 2; i++) {
                int c = tid + i * 256;
                int row = c >> 4, nc = c & 15;
                CP_ASYNC16(uBs + stage * BSTAGE_B + (row * BSTR + nc * 8) * 2,
                           B + (size_t)(k0 + row) * ldb + bn + nc * 8);
            }
        }
        CP_COMMIT();
    };

    const int nIter = K / BK;
    load_stage(0, 0);
    if (nIter > 1) load_stage(1, BK);

    const int a_row = (lane & 15);
    const int a_kc  = (lane >> 4);
    const int bnk_r = (lane & 7) + ((lane >> 4) << 3);
    const int bnk_k = (lane >> 3) & 1;
    const int bkn_r = (lane & 7) + (((lane >> 3) & 1) << 3);
    const int bkn_n = (lane >> 4);

    int stage = 0;
    for (int it = 0; it < nIter; it++) {
        if (it + 1 < nIter) {
            asm volatile("cp.async.wait_group 1;");
        } else {
            asm volatile("cp.async.wait_group 0;");
        }
        __syncthreads();

        if (it + 2 < nIter) {
            int ls = stage + 2; if (ls >= NSTAGE) ls -= NSTAGE;
            load_stage(ls, (it + 2) * BK);
        }

        const uint32_t aBase = uAs + stage * ASTAGE_B;
        const uint32_t bBase = uBs + stage * BSTAGE_B;

        #pragma unroll
        for (int ks = 0; ks < 2; ks++) {
            uint32_t a[4][4];
            #pragma unroll
            for (int mt = 0; mt < 4; mt++) {
                uint32_t addr = aBase +
                    ((wm * 64 + mt * 16 + a_row) * ASTR + ks * 16 + a_kc * 8) * 2;
                LDSM4(a[mt][0], a[mt][1], a[mt][2], a[mt][3], addr);
            }
            uint32_t bq[2][4];
            #pragma unroll
            for (int h = 0; h < 2; h++) {
                if (BMODE == 0) {
                    uint32_t addr = bBase +
                        ((wn * 32 + h * 16 + bnk_r) * BSTR + ks * 16 + bnk_k * 8) * 2;
                    LDSM4(bq[h][0], bq[h][1], bq[h][2], bq[h][3], addr);
                } else {
                    uint32_t addr = bBase +
                        ((ks * 16 + bkn_r) * BSTR + wn * 32 + h * 16 + bkn_n * 8) * 2;
                    LDSM4T(bq[h][0], bq[h][1], bq[h][2], bq[h][3], addr);
                }
            }
            #pragma unroll
            for (int mt = 0; mt < 4; mt++)
                #pragma unroll
                for (int nt = 0; nt < 4; nt++)
                    mma_bf16(acc[mt][nt][0], acc[mt][nt][1], acc[mt][nt][2], acc[mt][nt][3],
                             a[mt][0], a[mt][1], a[mt][2], a[mt][3],
                             bq[nt >> 1][(nt & 1) * 2], bq[nt >> 1][(nt & 1) * 2 + 1]);
        }
        __syncthreads();
        stage++; if (stage >= NSTAGE) stage = 0;
    }

    // epilogue
    #pragma unroll
    for (int mt = 0; mt < 4; mt++) {
        int r0 = bm + wm * 64 + mt * 16 + g;
        #pragma unroll
        for (int nt = 0; nt < 4; nt++) {
            int col = bn + wn * 32 + nt * 8 + 2 * t;
            float2 bb = make_float2(0.f, 0.f);
            if (HAS_BIAS) bb = *(const float2*)(bias + col);

            float v0 = acc[mt][nt][0] * alpha + bb.x;
            float v1 = acc[mt][nt][1] * alpha + bb.y;
            float v2 = acc[mt][nt][2] * alpha + bb.x;
            float v3 = acc[mt][nt][3] * alpha + bb.y;
            if (HAS_RES) {
                const float* rp = res + (size_t)blockIdx.z * sC;
                float2 ra = *(const float2*)(rp + (size_t)r0 * N + col);
                float2 rb = *(const float2*)(rp + (size_t)(r0 + 8) * N + col);
                v0 += ra.x; v1 += ra.y; v2 += rb.x; v3 += rb.y;
            }
            if (OUT_BF16) {
                bf16* C = (bf16*)Cout + (size_t)blockIdx.z * sC;
                *(__nv_bfloat162*)(C + (size_t)r0 * N + col)       = __floats2bfloat162_rn(v0, v1);
                *(__nv_bfloat162*)(C + (size_t)(r0 + 8) * N + col) = __floats2bfloat162_rn(v2, v3);
            } else {
                float* C = (float*)Cout + (size_t)blockIdx.z * sC;
                *(float2*)(C + (size_t)r0 * N + col)       = make_float2(v0, v1);
                *(float2*)(C + (size_t)(r0 + 8) * N + col) = make_float2(v2, v3);
            }
        }
    }
}

// ---------------- row softmax over 4096 keys: bf16 in-place ----------------
__global__ void softmax_rows_kernel(bf16* __restrict__ S) {
    bf16* p = S + (size_t)blockIdx.x * HW;
    const int tid = threadIdx.x;
    const int lane = tid & 31, wid = tid >> 5;
    __shared__ float shm[8], shs[8];
    __shared__ float bmax, bsum;

    // 16 bf16 per thread = 2x 16B loads
    float v[16];
    float mx = -CUDART_INF_F;
    #pragma unroll
    for (int i = 0; i < 2; i++) {
        uint4 raw = *(const uint4*)(p + i * 2048 + tid * 8);
        const __nv_bfloat162* h2 = (const __nv_bfloat162*)&raw;
        #pragma unroll
        for (int j = 0; j < 4; j++) {
            float2 f = __bfloat1622float2(h2[j]);
            v[i * 8 + j * 2 + 0] = f.x;
            v[i * 8 + j * 2 + 1] = f.y;
            mx = fmaxf(mx, fmaxf(f.x, f.y));
        }
    }
    #pragma unroll
    for (int o = 16; o > 0; o >>= 1) mx = fmaxf(mx, __shfl_xor_sync(0xffffffffu, mx, o));
    if (lane == 0) shm[wid] = mx;
    __syncthreads();
    if (tid == 0) {
        float t = shm[0];
        #pragma unroll
        for (int i = 1; i < 8; i++) t = fmaxf(t, shm[i]);
        bmax = t;
    }
    __syncthreads();
    mx = bmax;

    float sum = 0.f;
    #pragma unroll
    for (int i = 0; i < 16; i++) { v[i] = __expf(v[i] - mx); sum += v[i]; }
    #pragma unroll
    for (int o = 16; o > 0; o >>= 1) sum += __shfl_xor_sync(0xffffffffu, sum, o);
    if (lane == 0) shs[wid] = sum;
    __syncthreads();
    if (tid == 0) {
        float t = 0.f;
        #pragma unroll
        for (int i = 0; i < 8; i++) t += shs[i];
        bsum = 1.0f / t;
    }
    __syncthreads();
    const float inv = bsum;

    #pragma unroll
    for (int i = 0; i < 2; i++) {
        uint4 raw;
        __nv_bfloat162* h2 = (__nv_bfloat162*)&raw;
        #pragma unroll
        for (int j = 0; j < 4; j++)
            h2[j] = __floats2bfloat162_rn(v[i * 8 + j * 2 + 0] * inv,
                                          v[i * 8 + j * 2 + 1] * inv);
        *(uint4*)(p + i * 2048 + tid * 8) = raw;
    }
}

// ---------------- launch ----------------
extern "C" void kernel_launch(void* const* d_in, const int* in_sizes, int n_in,
                              void* d_out, int out_size) {
    const float* x        = (const float*)d_in[0];
    const float* gn_scale = (const float*)d_in[1];
    const float* gn_bias  = (const float*)d_in[2];
    const float* wq = (const float*)d_in[3];  const float* bq = (const float*)d_in[4];
    const float* wk = (const float*)d_in[5];  const float* bk = (const float*)d_in[6];
    const float* wv = (const float*)d_in[7];  const float* bv = (const float*)d_in[8];
    const float* wo = (const float*)d_in[9];  const float* bo = (const float*)d_in[10];
    float* out = (float*)d_out;

    bf16 *hn, *qkv, *s, *o, *wqkvp, *wop;
    float *bqkvp;
    cudaGetSymbolAddress((void**)&hn,    g_hn);
    cudaGetSymbolAddress((void**)&qkv,   g_qkv);
    cudaGetSymbolAddress((void**)&s,     g_s);
    cudaGetSymbolAddress((void**)&o,     g_o);
    cudaGetSymbolAddress((void**)&wqkvp, g_wqkv);
    cudaGetSymbolAddress((void**)&wop,   g_wo);
    cudaGetSymbolAddress((void**)&bqkvp, g_bqkv);

    // 1) GroupNorm + weight prep
    gn_stats_kernel<<<BATCH * NGROUPS, 256>>>(x);
    gn_apply_kernel<<<(NTOK * C_DIM / 4) / 256, 256>>>(x, gn_scale, gn_bias);
    prep_weights_kernel<<<(C_DIM * C_DIM) / 256, 256>>>(wq, wk, wv, wo, bq, bk, bv);

    dim3 blk(256);
    // 2) fused QKV projection: [16384,512] @ [512,1536] -> g_qkv bf16
    dim3 gqkv(QKV_N / 128, NTOK / 128, 1);
    gemm_bf16<0, true, false, true><<<gqkv, blk>>>(hn, wqkvp, bqkvp, nullptr, qkv,
        NTOK, QKV_N, C_DIM, C_DIM, C_DIM, 1.0f, 0, 0, 0);

    const bf16* qp = qkv;
    const bf16* kp = qkv + 512;
    const bf16* vp = qkv + 1024;

    // 3) S = (Q @ K^T) * c^-0.5, batched; bf16 out
    dim3 gs(HW / 128, HW / 128, BATCH);
    gemm_bf16<0, false, false, true><<<gs, blk>>>(qp, kp, nullptr, nullptr, s,
        HW, HW, C_DIM, QKV_N, QKV_N, SM_SCALE,
        (size_t)HW * QKV_N, (size_t)HW * QKV_N, (size_t)HW * HW);

    // 4) softmax in place (bf16)
    softmax_rows_kernel<<<NTOK, 256>>>(s);

    // 5) O = P @ V, batched; V rows are tokens with stride QKV_N -> BMODE 1
    dim3 gpv(C_DIM / 128, HW / 128, BATCH);
    gemm_bf16<1, false, false, true><<<gpv, blk>>>(s, vp, nullptr, nullptr, o,
        HW, C_DIM, HW, HW, QKV_N, 1.0f,
        (size_t)HW * HW, (size_t)HW * QKV_N, (size_t)HW * C_DIM);

    // 6) out = x + O @ wo + bo ; fp32 out
    dim3 gproj(C_DIM / 128, NTOK / 128, 1);
    gemm_bf16<0, true, true, false><<<gproj, blk>>>(o, wop, bo, x, out,
        NTOK, C_DIM, C_DIM, C_DIM, C_DIM, 1.0f, 0, 0, 0);
}

// round 7
// speedup vs baseline: 6.4812x; 1.0008x over previous
#include <cuda_runtime.h>
#include <cuda_bf16.h>
#include <math_constants.h>
#include <cstdint>

// ---------------- problem constants ----------------
#define C_DIM   512
#define NGROUPS 32
#define GSIZE   16
#define BATCH   4
#define HW      4096
#define NTOK    16384
#define EPS     1e-6f
#define SM_SCALE 0.04419417382415922f   // 512^-0.5
#define QKV_N   1536

typedef __nv_bfloat16 bf16;

// ---------------- device scratch ----------------
__device__ float g_mean[BATCH * NGROUPS];
__device__ float g_rstd[BATCH * NGROUPS];
__device__ bf16  g_hn  [NTOK * C_DIM];
__device__ bf16  g_qkv [(size_t)NTOK * QKV_N];        // 48 MB
__device__ bf16  g_s   [(size_t)BATCH * HW * HW];     // 128 MB (scores -> probs in place)
__device__ bf16  g_o   [NTOK * C_DIM];
__device__ bf16  g_wqkv[QKV_N * C_DIM];               // [n][k] bf16
__device__ bf16  g_wo  [C_DIM * C_DIM];               // [n][k] bf16
__device__ float g_bqkv[QKV_N];

// ---------------- helpers ----------------
__device__ __forceinline__ uint32_t smem_u32(const void* p) {
    return (uint32_t)__cvta_generic_to_shared(p);
}
#define CP_ASYNC16(dst, src) \
    asm volatile("cp.async.cg.shared.global [%0], [%1], 16;" :: "r"(dst), "l"(src))
#define CP_COMMIT() asm volatile("cp.async.commit_group;")

#define LDSM4(r0,r1,r2,r3, addr) \
    asm volatile("ldmatrix.sync.aligned.m8n8.x4.shared.b16 {%0,%1,%2,%3}, [%4];" \
        : "=r"(r0),"=r"(r1),"=r"(r2),"=r"(r3) : "r"(addr))
#define LDSM4T(r0,r1,r2,r3, addr) \
    asm volatile("ldmatrix.sync.aligned.m8n8.x4.trans.shared.b16 {%0,%1,%2,%3}, [%4];" \
        : "=r"(r0),"=r"(r1),"=r"(r2),"=r"(r3) : "r"(addr))

__device__ __forceinline__ void mma_bf16(float& c0, float& c1, float& c2, float& c3,
                                         uint32_t a0, uint32_t a1, uint32_t a2, uint32_t a3,
                                         uint32_t b0, uint32_t b1) {
    asm volatile(
        "mma.sync.aligned.m16n8k16.row.col.f32.bf16.bf16.f32 "
        "{%0,%1,%2,%3}, {%4,%5,%6,%7}, {%8,%9}, {%0,%1,%2,%3};"
        : "+f"(c0), "+f"(c1), "+f"(c2), "+f"(c3)
        : "r"(a0), "r"(a1), "r"(a2), "r"(a3), "r"(b0), "r"(b1));
}

// ---------------- GroupNorm stats ----------------
__global__ void gn_stats_kernel(const float* __restrict__ x) {
    int bg = blockIdx.x;
    int b  = bg / NGROUPS;
    int g  = bg % NGROUPS;
    const float* base = x + (size_t)b * HW * C_DIM + g * GSIZE;

    float s = 0.f, ss = 0.f;
    for (int p = threadIdx.x; p < HW; p += blockDim.x) {
        const float4* v4 = (const float4*)(base + (size_t)p * C_DIM);
        #pragma unroll
        for (int j = 0; j < 4; j++) {
            float4 v = v4[j];
            s  += v.x + v.y + v.z + v.w;
            ss += v.x*v.x + v.y*v.y + v.z*v.z + v.w*v.w;
        }
    }
    __shared__ float shs[8], shss[8];
    int lane = threadIdx.x & 31, wid = threadIdx.x >> 5;
    #pragma unroll
    for (int o = 16; o > 0; o >>= 1) {
        s  += __shfl_xor_sync(0xffffffffu, s,  o);
        ss += __shfl_xor_sync(0xffffffffu, ss, o);
    }
    if (lane == 0) { shs[wid] = s; shss[wid] = ss; }
    __syncthreads();
    if (threadIdx.x == 0) {
        float ts = 0.f, tss = 0.f;
        #pragma unroll
        for (int i = 0; i < 8; i++) { ts += shs[i]; tss += shss[i]; }
        const float invn = 1.0f / (float)(HW * GSIZE);
        float mean = ts * invn;
        float var  = tss * invn - mean * mean;
        g_mean[bg] = mean;
        g_rstd[bg] = rsqrtf(var + EPS);
    }
}

// ---------------- GroupNorm apply (writes bf16 hn) ----------------
__global__ void gn_apply_kernel(const float* __restrict__ x,
                                const float* __restrict__ scale,
                                const float* __restrict__ bias) {
    size_t i = (size_t)blockIdx.x * blockDim.x + threadIdx.x;   // float4 index
    int    c4 = (int)(i % (C_DIM / 4));
    size_t t  = i / (C_DIM / 4);
    int    b  = (int)(t / HW);
    int    g  = (c4 * 4) / GSIZE;

    float mean = g_mean[b * NGROUPS + g];
    float rstd = g_rstd[b * NGROUPS + g];
    float4 xv = ((const float4*)x)[i];
    float4 sc = ((const float4*)scale)[c4];
    float4 bi = ((const float4*)bias)[c4];
    float r0 = (xv.x - mean) * rstd * sc.x + bi.x;
    float r1 = (xv.y - mean) * rstd * sc.y + bi.y;
    float r2 = (xv.z - mean) * rstd * sc.z + bi.z;
    float r3 = (xv.w - mean) * rstd * sc.w + bi.w;
    __nv_bfloat162* o = (__nv_bfloat162*)(g_hn + i * 4);
    o[0] = __floats2bfloat162_rn(r0, r1);
    o[1] = __floats2bfloat162_rn(r2, r3);
}

// ---------------- weight prep: transpose + bf16 + concat ----------------
__global__ void prep_weights_kernel(const float* __restrict__ wq,
                                    const float* __restrict__ wk,
                                    const float* __restrict__ wv,
                                    const float* __restrict__ wo,
                                    const float* __restrict__ bq,
                                    const float* __restrict__ bk,
                                    const float* __restrict__ bv) {
    int i = blockIdx.x * blockDim.x + threadIdx.x;  // < 512*512, i = k*512+n
    int k = i >> 9, n = i & 511;
    g_wqkv[(n)        * C_DIM + k] = __float2bfloat16_rn(wq[i]);
    g_wqkv[(n + 512)  * C_DIM + k] = __float2bfloat16_rn(wk[i]);
    g_wqkv[(n + 1024) * C_DIM + k] = __float2bfloat16_rn(wv[i]);
    g_wo  [n * C_DIM + k]          = __float2bfloat16_rn(wo[i]);
    if (i < 512) {
        g_bqkv[i]        = bq[i];
        g_bqkv[i + 512]  = bk[i];
        g_bqkv[i + 1024] = bv[i];
    }
}

// ---------------- bf16 tensor-core GEMM (3-stage cp.async) ----------------
// C = alpha * A @ B' [+ bias] [+ res]
// A: [M,K] bf16, row stride lda.
// BMODE 0: B stored [N,K] (row stride ldb) -> ldmatrix non-trans
// BMODE 1: B stored [K,N] (row stride ldb) -> ldmatrix trans
// 128x128x32 block tile, 8 warps (2x4), 64x32 warp tile.
template<int BMODE, bool HAS_BIAS, bool HAS_RES, bool OUT_BF16>
__global__ void __launch_bounds__(256, 2)
gemm_bf16(const bf16* __restrict__ A, const bf16* __restrict__ B,
          const float* __restrict__ bias, const float* __restrict__ res,
          void* __restrict__ Cout,
          int M, int N, int K, int lda, int ldb, float alpha,
          size_t sA, size_t sB, size_t sC) {
    constexpr int BM = 128, BN = 128, BK = 32;
    constexpr int NSTAGE = 3;
    constexpr int ASTR = 40;                        // bf16 units (80B rows)
    constexpr int BSTR = (BMODE == 0) ? 40 : 136;
    constexpr int BROWS = (BMODE == 0) ? 128 : 32;
    constexpr int ASTAGE_B = BM * ASTR * 2;
    constexpr int BSTAGE_B = BROWS * BSTR * 2;

    __shared__ __align__(16) bf16 As[NSTAGE][BM * ASTR];
    __shared__ __align__(16) bf16 Bs[NSTAGE][BROWS * BSTR];

    A += (size_t)blockIdx.z * sA;
    B += (size_t)blockIdx.z * sB;

    const int bm = blockIdx.y * BM;
    const int bn = blockIdx.x * BN;
    const int tid  = threadIdx.x;
    const int lane = tid & 31;
    const int wid  = tid >> 5;
    const int g    = lane >> 2;
    const int t    = lane & 3;
    const int wm   = wid >> 2;
    const int wn   = wid & 3;

    const uint32_t uAs = smem_u32(&As[0][0]);
    const uint32_t uBs = smem_u32(&Bs[0][0]);

    float acc[4][4][4];
    #pragma unroll
    for (int i = 0; i < 4; i++)
        #pragma unroll
        for (int j = 0; j < 4; j++)
            #pragma unroll
            for (int r = 0; r < 4; r++) acc[i][j][r] = 0.f;

    auto load_stage = [&](int stage, int k0) {
        #pragma unroll
        for (int i = 0; i < 2; i++) {
            int c = tid + i * 256;
            int row = c >> 2, kc = c & 3;
            CP_ASYNC16(uAs + stage * ASTAGE_B + (row * ASTR + kc * 8) * 2,
                       A + (size_t)(bm + row) * lda + k0 + kc * 8);
        }
        if (BMODE == 0) {
            #pragma unroll
            for (int i = 0; i < 2; i++) {
                int c = tid + i * 256;
                int row = c >> 2, kc = c & 3;
                CP_ASYNC16(uBs + stage * BSTAGE_B + (row * BSTR + kc * 8) * 2,
                           B + (size_t)(bn + row) * ldb + k0 + kc * 8);
            }
        } else {
            #pragma unroll
            for (int i = 0; i < 2; i++) {
                int c = tid + i * 256;
                int row = c >> 4, nc = c & 15;
                CP_ASYNC16(uBs + stage * BSTAGE_B + (row * BSTR + nc * 8) * 2,
                           B + (size_t)(k0 + row) * ldb + bn + nc * 8);
            }
        }
        CP_COMMIT();
    };

    const int nIter = K / BK;
    load_stage(0, 0);
    if (nIter > 1) load_stage(1, BK);

    const int a_row = (lane & 15);
    const int a_kc  = (lane >> 4);
    const int bnk_r = (lane & 7) + ((lane >> 4) << 3);
    const int bnk_k = (lane >> 3) & 1;
    const int bkn_r = (lane & 7) + (((lane >> 3) & 1) << 3);
    const int bkn_n = (lane >> 4);

    int stage = 0;
    for (int it = 0; it < nIter; it++) {
        if (it + 1 < nIter) {
            asm volatile("cp.async.wait_group 1;");
        } else {
            asm volatile("cp.async.wait_group 0;");
        }
        __syncthreads();

        if (it + 2 < nIter) {
            int ls = stage + 2; if (ls >= NSTAGE) ls -= NSTAGE;
            load_stage(ls, (it + 2) * BK);
        }

        const uint32_t aBase = uAs + stage * ASTAGE_B;
        const uint32_t bBase = uBs + stage * BSTAGE_B;

        #pragma unroll
        for (int ks = 0; ks < 2; ks++) {
            uint32_t a[4][4];
            #pragma unroll
            for (int mt = 0; mt < 4; mt++) {
                uint32_t addr = aBase +
                    ((wm * 64 + mt * 16 + a_row) * ASTR + ks * 16 + a_kc * 8) * 2;
                LDSM4(a[mt][0], a[mt][1], a[mt][2], a[mt][3], addr);
            }
            uint32_t bq[2][4];
            #pragma unroll
            for (int h = 0; h < 2; h++) {
                if (BMODE == 0) {
                    uint32_t addr = bBase +
                        ((wn * 32 + h * 16 + bnk_r) * BSTR + ks * 16 + bnk_k * 8) * 2;
                    LDSM4(bq[h][0], bq[h][1], bq[h][2], bq[h][3], addr);
                } else {
                    uint32_t addr = bBase +
                        ((ks * 16 + bkn_r) * BSTR + wn * 32 + h * 16 + bkn_n * 8) * 2;
                    LDSM4T(bq[h][0], bq[h][1], bq[h][2], bq[h][3], addr);
                }
            }
            #pragma unroll
            for (int mt = 0; mt < 4; mt++)
                #pragma unroll
                for (int nt = 0; nt < 4; nt++)
                    mma_bf16(acc[mt][nt][0], acc[mt][nt][1], acc[mt][nt][2], acc[mt][nt][3],
                             a[mt][0], a[mt][1], a[mt][2], a[mt][3],
                             bq[nt >> 1][(nt & 1) * 2], bq[nt >> 1][(nt & 1) * 2 + 1]);
        }
        __syncthreads();
        stage++; if (stage >= NSTAGE) stage = 0;
    }

    // epilogue
    #pragma unroll
    for (int mt = 0; mt < 4; mt++) {
        int r0 = bm + wm * 64 + mt * 16 + g;
        #pragma unroll
        for (int nt = 0; nt < 4; nt++) {
            int col = bn + wn * 32 + nt * 8 + 2 * t;
            float2 bb = make_float2(0.f, 0.f);
            if (HAS_BIAS) bb = *(const float2*)(bias + col);

            float v0 = acc[mt][nt][0] * alpha + bb.x;
            float v1 = acc[mt][nt][1] * alpha + bb.y;
            float v2 = acc[mt][nt][2] * alpha + bb.x;
            float v3 = acc[mt][nt][3] * alpha + bb.y;
            if (HAS_RES) {
                const float* rp = res + (size_t)blockIdx.z * sC;
                float2 ra = *(const float2*)(rp + (size_t)r0 * N + col);
                float2 rb = *(const float2*)(rp + (size_t)(r0 + 8) * N + col);
                v0 += ra.x; v1 += ra.y; v2 += rb.x; v3 += rb.y;
            }
            if (OUT_BF16) {
                bf16* C = (bf16*)Cout + (size_t)blockIdx.z * sC;
                *(__nv_bfloat162*)(C + (size_t)r0 * N + col)       = __floats2bfloat162_rn(v0, v1);
                *(__nv_bfloat162*)(C + (size_t)(r0 + 8) * N + col) = __floats2bfloat162_rn(v2, v3);
            } else {
                float* C = (float*)Cout + (size_t)blockIdx.z * sC;
                *(float2*)(C + (size_t)r0 * N + col)       = make_float2(v0, v1);
                *(float2*)(C + (size_t)(r0 + 8) * N + col) = make_float2(v2, v3);
            }
        }
    }
}

// ---------------- row softmax over 4096 keys: bf16 in-place ----------------
__global__ void softmax_rows_kernel(bf16* __restrict__ S) {
    bf16* p = S + (size_t)blockIdx.x * HW;
    const int tid = threadIdx.x;
    const int lane = tid & 31, wid = tid >> 5;
    __shared__ float shm[8], shs[8];
    __shared__ float bmax, bsum;

    // 16 bf16 per thread = 2x 16B loads
    float v[16];
    float mx = -CUDART_INF_F;
    #pragma unroll
    for (int i = 0; i < 2; i++) {
        uint4 raw = *(const uint4*)(p + i * 2048 + tid * 8);
        const __nv_bfloat162* h2 = (const __nv_bfloat162*)&raw;
        #pragma unroll
        for (int j = 0; j < 4; j++) {
            float2 f = __bfloat1622float2(h2[j]);
            v[i * 8 + j * 2 + 0] = f.x;
            v[i * 8 + j * 2 + 1] = f.y;
            mx = fmaxf(mx, fmaxf(f.x, f.y));
        }
    }
    #pragma unroll
    for (int o = 16; o > 0; o >>= 1) mx = fmaxf(mx, __shfl_xor_sync(0xffffffffu, mx, o));
    if (lane == 0) shm[wid] = mx;
    __syncthreads();
    if (tid == 0) {
        float t = shm[0];
        #pragma unroll
        for (int i = 1; i < 8; i++) t = fmaxf(t, shm[i]);
        bmax = t;
    }
    __syncthreads();
    mx = bmax;

    float sum = 0.f;
    #pragma unroll
    for (int i = 0; i < 16; i++) { v[i] = __expf(v[i] - mx); sum += v[i]; }
    #pragma unroll
    for (int o = 16; o > 0; o >>= 1) sum += __shfl_xor_sync(0xffffffffu, sum, o);
    if (lane == 0) shs[wid] = sum;
    __syncthreads();
    if (tid == 0) {
        float t = 0.f;
        #pragma unroll
        for (int i = 0; i < 8; i++) t += shs[i];
        bsum = 1.0f / t;
    }
    __syncthreads();
    const float inv = bsum;

    #pragma unroll
    for (int i = 0; i < 2; i++) {
        uint4 raw;
        __nv_bfloat162* h2 = (__nv_bfloat162*)&raw;
        #pragma unroll
        for (int j = 0; j < 4; j++)
            h2[j] = __floats2bfloat162_rn(v[i * 8 + j * 2 + 0] * inv,
                                          v[i * 8 + j * 2 + 1] * inv);
        *(uint4*)(p + i * 2048 + tid * 8) = raw;
    }
}

// ---------------- launch ----------------
extern "C" void kernel_launch(void* const* d_in, const int* in_sizes, int n_in,
                              void* d_out, int out_size) {
    const float* x        = (const float*)d_in[0];
    const float* gn_scale = (const float*)d_in[1];
    const float* gn_bias  = (const float*)d_in[2];
    const float* wq = (const float*)d_in[3];  const float* bq = (const float*)d_in[4];
    const float* wk = (const float*)d_in[5];  const float* bk = (const float*)d_in[6];
    const float* wv = (const float*)d_in[7];  const float* bv = (const float*)d_in[8];
    const float* wo = (const float*)d_in[9];  const float* bo = (const float*)d_in[10];
    float* out = (float*)d_out;

    bf16 *hn, *qkv, *s, *o, *wqkvp, *wop;
    float *bqkvp;
    cudaGetSymbolAddress((void**)&hn,    g_hn);
    cudaGetSymbolAddress((void**)&qkv,   g_qkv);
    cudaGetSymbolAddress((void**)&s,     g_s);
    cudaGetSymbolAddress((void**)&o,     g_o);
    cudaGetSymbolAddress((void**)&wqkvp, g_wqkv);
    cudaGetSymbolAddress((void**)&wop,   g_wo);
    cudaGetSymbolAddress((void**)&bqkvp, g_bqkv);

    // 1) GroupNorm + weight prep
    gn_stats_kernel<<<BATCH * NGROUPS, 256>>>(x);
    gn_apply_kernel<<<(NTOK * C_DIM / 4) / 256, 256>>>(x, gn_scale, gn_bias);
    prep_weights_kernel<<<(C_DIM * C_DIM) / 256, 256>>>(wq, wk, wv, wo, bq, bk, bv);

    dim3 blk(256);
    // 2) fused QKV projection: [16384,512] @ [512,1536] -> g_qkv bf16
    dim3 gqkv(QKV_N / 128, NTOK / 128, 1);
    gemm_bf16<0, true, false, true><<<gqkv, blk>>>(hn, wqkvp, bqkvp, nullptr, qkv,
        NTOK, QKV_N, C_DIM, C_DIM, C_DIM, 1.0f, 0, 0, 0);

    const bf16* qp = qkv;
    const bf16* kp = qkv + 512;
    const bf16* vp = qkv + 1024;

    // 3) S = (Q @ K^T) * c^-0.5, batched; bf16 out
    dim3 gs(HW / 128, HW / 128, BATCH);
    gemm_bf16<0, false, false, true><<<gs, blk>>>(qp, kp, nullptr, nullptr, s,
        HW, HW, C_DIM, QKV_N, QKV_N, SM_SCALE,
        (size_t)HW * QKV_N, (size_t)HW * QKV_N, (size_t)HW * HW);

    // 4) softmax in place (bf16)
    softmax_rows_kernel<<<NTOK, 256>>>(s);

    // 5) O = P @ V, batched; V rows are tokens with stride QKV_N -> BMODE 1
    dim3 gpv(C_DIM / 128, HW / 128, BATCH);
    gemm_bf16<1, false, false, true><<<gpv, blk>>>(s, vp, nullptr, nullptr, o,
        HW, C_DIM, HW, HW, QKV_N, 1.0f,
        (size_t)HW * HW, (size_t)HW * QKV_N, (size_t)HW * C_DIM);

    // 6) out = x + O @ wo + bo ; fp32 out
    dim3 gproj(C_DIM / 128, NTOK / 128, 1);
    gemm_bf16<0, true, true, false><<<gproj, blk>>>(o, wop, bo, x, out,
        NTOK, C_DIM, C_DIM, C_DIM, C_DIM, 1.0f, 0, 0, 0);
}